// round 5
// baseline (speedup 1.0000x reference)
#include <cuda_runtime.h>
#include <cuda_bf16.h>
#include <math.h>

// ---------------------------------------------------------------------------
// SnakeScanBranch: dwconv5x5 -> groupnorm+gelu -> pointwise -> offset ->
// grid_sample (y-only deform) -> seq -> in_proj GEMM -> conv1d+silu ->
// selective scan -> gated RMSNorm -> out GEMM -> NCHW.
// All fp32 this round (correctness + baseline for ncu).
// ---------------------------------------------------------------------------

#define Bb 8
#define Cc 128
#define Hh 128
#define Ww 128
#define HW 16384           // Hh*Ww
#define D_INNER 256
#define D_STATE 64
#define HEADDIM 32
#define NHEADS 8
#define D_XBC 384
#define D_INPROJ 648
#define BS 1024            // Bb*Hh sequences
#define LL 128             // Ww
#define MM 131072          // BS*LL
#define OUT2D_ELEMS 16777216
#define OFF_ELEMS 131072

// ---- scratch (device globals; no allocation at runtime) -------------------
__device__ float g_buf1[OUT2D_ELEMS];           // tmp1 -> seq -> out_gemm (reused)
__device__ float g_zx[(size_t)MM * D_INPROJ];   // 84.9M floats
__device__ float g_xbcc[(size_t)MM * D_XBC];    // 50.3M floats
__device__ float g_dt[MM * NHEADS];
__device__ float g_ys[(size_t)MM * D_INNER];    // ys -> y3 in place
__device__ float g_off[OFF_ELEMS];
__device__ float g_stats[Bb * 8 * 2];

// ---------------------------------------------------------------------------
// K1: depthwise 5x5 conv, SAME zero padding
// ---------------------------------------------------------------------------
__global__ __launch_bounds__(256) void k_dwconv(const float* __restrict__ x,
                                                const float* __restrict__ w) {
    int idx = blockIdx.x * 256 + threadIdx.x;            // over B*C*H*W
    int xx = idx & 127;
    int yy = (idx >> 7) & 127;
    int c  = (idx >> 14) & 127;
    const float* wp = w + c * 25;
    const float* plane = x + (idx - yy * Ww - xx);        // start of (b,c) plane
    float acc = 0.0f;
#pragma unroll
    for (int ky = 0; ky < 5; ky++) {
        int sy = yy + ky - 2;
        if (sy < 0 || sy > 127) continue;
        const float* row = plane + sy * Ww;
#pragma unroll
        for (int kx = 0; kx < 5; kx++) {
            int sx = xx + kx - 2;
            if (sx < 0 || sx > 127) continue;
            acc += __ldg(row + sx) * __ldg(wp + ky * 5 + kx);
        }
    }
    g_buf1[idx] = acc;
}

// ---------------------------------------------------------------------------
// K2: groupnorm stats per (b, group): mean + rstd over 16ch*HW
// ---------------------------------------------------------------------------
__global__ __launch_bounds__(256) void k_gnstats() {
    int b = blockIdx.x, g = blockIdx.y;
    const float* p = g_buf1 + ((size_t)b * Cc + g * 16) * HW;
    float s = 0.0f, ss = 0.0f;
    for (int i = threadIdx.x; i < 16 * HW; i += 256) {
        float v = p[i];
        s += v; ss += v * v;
    }
    __shared__ float rs[256], rss[256];
    rs[threadIdx.x] = s; rss[threadIdx.x] = ss;
    __syncthreads();
    for (int o = 128; o > 0; o >>= 1) {
        if (threadIdx.x < o) { rs[threadIdx.x] += rs[threadIdx.x + o]; rss[threadIdx.x] += rss[threadIdx.x + o]; }
        __syncthreads();
    }
    if (threadIdx.x == 0) {
        const float inv = 1.0f / (16.0f * HW);
        float mean = rs[0] * inv;
        float var  = rss[0] * inv - mean * mean;
        g_stats[(b * 8 + g) * 2]     = mean;
        g_stats[(b * 8 + g) * 2 + 1] = rsqrtf(var + 1e-5f);
    }
}

// ---------------------------------------------------------------------------
// K3: gelu(groupnorm) -> pointwise conv (C->1) -> tanh*8 offset
// ---------------------------------------------------------------------------
__global__ __launch_bounds__(256) void k_offset(const float* __restrict__ gn_g,
                                                const float* __restrict__ gn_b,
                                                const float* __restrict__ pw_w,
                                                const float* __restrict__ pw_b) {
    int idx = blockIdx.x * 256 + threadIdx.x;            // b*HW + pix
    int b = idx >> 14;
    int pix = idx & 16383;
    float acc = 0.0f;
    for (int c = 0; c < Cc; c++) {
        float v = g_buf1[((size_t)b * Cc + c) * HW + pix];
        int grp = c >> 4;
        float mean = __ldg(&g_stats[(b * 8 + grp) * 2]);
        float rstd = __ldg(&g_stats[(b * 8 + grp) * 2 + 1]);
        float u = (v - mean) * rstd * __ldg(gn_g + c) + __ldg(gn_b + c);
        float ge = 0.5f * u * (1.0f + erff(u * 0.70710678118654752440f));
        acc += __ldg(pw_w + c) * ge;
    }
    acc += __ldg(pw_b);
    g_off[idx] = tanhf(acc) * 8.0f;
}

// ---------------------------------------------------------------------------
// K4: grid sample (bilinear, border) + transpose to seq[(b*H+y)*W + x][c]
// grid_x == base_x (no x offset); grid_y = clip(base_y + off_n, -1, 1)
// ---------------------------------------------------------------------------
__global__ __launch_bounds__(256) void k_sample(const float* __restrict__ x) {
    int by = blockIdx.x;                   // b*H + y
    int b = by >> 7, y = by & 127;
    int x0g = blockIdx.y * 64;
    __shared__ float tile[64][129];
    __shared__ int s_y0[64], s_y1[64], s_x0[64], s_x1[64];
    __shared__ float s_wx[64], s_wy[64];
    int tid = threadIdx.x;
    if (tid < 64) {
        int xg = x0g + tid;
        float off_n = g_off[by * Ww + xg] * (2.0f / 127.0f);
        float byv = -1.0f + y  * (2.0f / 127.0f);
        float bxv = -1.0f + xg * (2.0f / 127.0f);
        float gyv = fminf(fmaxf(byv + off_n, -1.0f), 1.0f);
        float gx = fminf(fmaxf((bxv + 1.0f) * 0.5f * 127.0f, 0.0f), 127.0f);
        float gy = fminf(fmaxf((gyv + 1.0f) * 0.5f * 127.0f, 0.0f), 127.0f);
        float fx0 = floorf(gx), fy0 = floorf(gy);
        s_wx[tid] = gx - fx0;
        s_wy[tid] = gy - fy0;
        int x0i = (int)fx0, y0i = (int)fy0;
        s_x0[tid] = x0i; s_y0[tid] = y0i;
        s_x1[tid] = min(x0i + 1, 127);
        s_y1[tid] = min(y0i + 1, 127);
    }
    __syncthreads();
    for (int i = tid; i < 64 * Cc; i += 256) {
        int xl = i & 63;
        int c = i >> 6;
        const float* pl = x + ((size_t)b * Cc + c) * HW;
        float wx = s_wx[xl], wy = s_wy[xl];
        int r0 = s_y0[xl] * Ww, r1 = s_y1[xl] * Ww;
        float v00 = __ldg(pl + r0 + s_x0[xl]);
        float v01 = __ldg(pl + r0 + s_x1[xl]);
        float v10 = __ldg(pl + r1 + s_x0[xl]);
        float v11 = __ldg(pl + r1 + s_x1[xl]);
        float top = v00 * (1.0f - wx) + v01 * wx;
        float bot = v10 * (1.0f - wx) + v11 * wx;
        tile[xl][c] = top * (1.0f - wy) + bot * wy;
    }
    __syncthreads();
    int cc = tid & 127;
    for (int xl = tid >> 7; xl < 64; xl += 2)
        g_buf1[((size_t)by * Ww + x0g + xl) * Cc + cc] = tile[xl][cc];
}

// ---------------------------------------------------------------------------
// SGEMM: C[m,n] = sum_k A[m,k] * B[n,k].  BM=128 BN=64 BK=16, 8x4/thread.
// ---------------------------------------------------------------------------
__global__ __launch_bounds__(256) void k_sgemm(const float* __restrict__ A,
                                               const float* __restrict__ Bm,
                                               float* __restrict__ Cm,
                                               int N, int K, int ldc) {
    __shared__ float As[16][132];
    __shared__ float Bs[16][68];
    int tid = threadIdx.x;
    int tx = tid & 15;           // n dir (x4)
    int ty = tid >> 4;           // m dir (x8)
    int m0 = blockIdx.y * 128;
    int n0 = blockIdx.x * 64;

    float acc[8][4];
#pragma unroll
    for (int i = 0; i < 8; i++)
#pragma unroll
        for (int j = 0; j < 4; j++) acc[i][j] = 0.0f;

    int ar = tid >> 2;           // 0..63
    int ak = (tid & 3) * 4;
    int bn = tid >> 2;
    int bk = (tid & 3) * 4;
    const float* Ab = A + (size_t)m0 * K;

    for (int kk = 0; kk < K; kk += 16) {
        float4 a0 = *(const float4*)(Ab + (size_t)ar * K + kk + ak);
        float4 a1 = *(const float4*)(Ab + (size_t)(ar + 64) * K + kk + ak);
        float4 bv = make_float4(0.f, 0.f, 0.f, 0.f);
        if (n0 + bn < N)
            bv = *(const float4*)(Bm + (size_t)(n0 + bn) * K + kk + bk);
        __syncthreads();
        As[ak + 0][ar] = a0.x; As[ak + 1][ar] = a0.y; As[ak + 2][ar] = a0.z; As[ak + 3][ar] = a0.w;
        As[ak + 0][ar + 64] = a1.x; As[ak + 1][ar + 64] = a1.y; As[ak + 2][ar + 64] = a1.z; As[ak + 3][ar + 64] = a1.w;
        Bs[bk + 0][bn] = bv.x; Bs[bk + 1][bn] = bv.y; Bs[bk + 2][bn] = bv.z; Bs[bk + 3][bn] = bv.w;
        __syncthreads();
#pragma unroll
        for (int k = 0; k < 16; k++) {
            float4 fa0 = *(const float4*)&As[k][ty * 8];
            float4 fa1 = *(const float4*)&As[k][ty * 8 + 4];
            float4 fb  = *(const float4*)&Bs[k][tx * 4];
            float av[8] = {fa0.x, fa0.y, fa0.z, fa0.w, fa1.x, fa1.y, fa1.z, fa1.w};
            float bw[4] = {fb.x, fb.y, fb.z, fb.w};
#pragma unroll
            for (int i = 0; i < 8; i++)
#pragma unroll
                for (int j = 0; j < 4; j++)
                    acc[i][j] += av[i] * bw[j];
        }
    }
#pragma unroll
    for (int i = 0; i < 8; i++) {
        int row = m0 + ty * 8 + i;
        int col = n0 + tx * 4;
        if (col + 3 < N) {
            *(float4*)(Cm + (size_t)row * ldc + col) =
                make_float4(acc[i][0], acc[i][1], acc[i][2], acc[i][3]);
        } else {
#pragma unroll
            for (int j = 0; j < 4; j++)
                if (col + j < N) Cm[(size_t)row * ldc + col + j] = acc[i][j];
        }
    }
}

// ---------------------------------------------------------------------------
// K6: causal depthwise conv1d (4 taps) over L on xBC channels + bias + silu
// ---------------------------------------------------------------------------
__global__ __launch_bounds__(256) void k_conv1d(const float* __restrict__ cw,
                                                const float* __restrict__ cb) {
    int idx = blockIdx.x * 256 + threadIdx.x;            // MM * 384
    int e = idx % D_XBC;
    int ml = idx / D_XBC;
    int l = ml & 127;
    int bs = ml >> 7;
    const float* src = g_zx + ((size_t)bs * LL) * D_INPROJ + D_INNER + e;
    float4 w = *(const float4*)(cw + e * 4);
    float acc = __ldg(cb + e);
    const float wt[4] = {w.x, w.y, w.z, w.w};
#pragma unroll
    for (int k = 0; k < 4; k++) {
        int lp = l - 3 + k;
        if (lp >= 0) acc += wt[k] * src[(size_t)lp * D_INPROJ];
    }
    g_xbcc[idx] = acc / (1.0f + expf(-acc));             // silu
}

// K6b: dt = softplus(raw + dt_bias)
__global__ __launch_bounds__(256) void k_dt(const float* __restrict__ dt_bias) {
    int idx = blockIdx.x * 256 + threadIdx.x;            // MM * 8
    int h = idx & 7;
    int m = idx >> 3;
    float v = g_zx[(size_t)m * D_INPROJ + 640 + h] + __ldg(dt_bias + h);
    g_dt[idx] = fmaxf(v, 0.0f) + log1pf(expf(-fabsf(v)));
}

// ---------------------------------------------------------------------------
// K7: selective scan. Block per (seq, head). 256 threads: thread = (d, s8),
// d = tid>>3 (0..31), each thread owns 8 state columns. State in registers.
// ---------------------------------------------------------------------------
#define SCAN_SMEM ((8192 + 8192 + 4096 + 128 + 128) * 4)
__global__ __launch_bounds__(256) void k_scan(const float* __restrict__ A_log,
                                              const float* __restrict__ Dskip) {
    extern __shared__ float sm[];
    float* sB  = sm;            // 128*64
    float* sC  = sB + 8192;     // 128*64
    float* sx  = sC + 8192;     // 128*32
    float* sdt = sx + 4096;     // 128
    float* sdA = sdt + 128;     // 128
    int bs = blockIdx.x, hh = blockIdx.y;
    int tid = threadIdx.x;
    float Ah = -expf(__ldg(A_log + hh));
    float Dh = __ldg(Dskip + hh);

    const float* base = g_xbcc + (size_t)bs * LL * D_XBC;
    for (int i = tid; i < 128 * 64; i += 256) {
        int l = i >> 6, s = i & 63;
        sB[i] = base[l * D_XBC + D_INNER + s];
        sC[i] = base[l * D_XBC + D_INNER + D_STATE + s];
    }
    for (int i = tid; i < 128 * 32; i += 256) {
        int l = i >> 5, d = i & 31;
        sx[i] = base[l * D_XBC + hh * HEADDIM + d];
    }
    if (tid < 128) {
        float v = g_dt[((size_t)bs * LL + tid) * NHEADS + hh];
        sdt[tid] = v;
        sdA[tid] = expf(v * Ah);
    }
    __syncthreads();

    int d = tid >> 3;
    int s8 = tid & 7;
    int sb = s8 * 8;
    float h[8] = {0, 0, 0, 0, 0, 0, 0, 0};
    float* ysout = g_ys + ((size_t)bs * LL) * D_INNER + hh * HEADDIM + d;

    for (int l = 0; l < LL; l++) {
        float dtv = sdt[l];
        float dA = sdA[l];
        float xv = sx[l * 32 + d];
        float cf = dtv * xv;
        float4 b0 = *(const float4*)&sB[l * 64 + sb];
        float4 b1 = *(const float4*)&sB[l * 64 + sb + 4];
        float4 c0 = *(const float4*)&sC[l * 64 + sb];
        float4 c1 = *(const float4*)&sC[l * 64 + sb + 4];
        float y = 0.0f;
        h[0] = h[0] * dA + cf * b0.x; y += h[0] * c0.x;
        h[1] = h[1] * dA + cf * b0.y; y += h[1] * c0.y;
        h[2] = h[2] * dA + cf * b0.z; y += h[2] * c0.z;
        h[3] = h[3] * dA + cf * b0.w; y += h[3] * c0.w;
        h[4] = h[4] * dA + cf * b1.x; y += h[4] * c1.x;
        h[5] = h[5] * dA + cf * b1.y; y += h[5] * c1.y;
        h[6] = h[6] * dA + cf * b1.z; y += h[6] * c1.z;
        h[7] = h[7] * dA + cf * b1.w; y += h[7] * c1.w;
        y += __shfl_down_sync(0xffffffffu, y, 4, 8);
        y += __shfl_down_sync(0xffffffffu, y, 2, 8);
        y += __shfl_down_sync(0xffffffffu, y, 1, 8);
        if (s8 == 0) ysout[(size_t)l * D_INNER] = y + Dh * xv;
    }
}

// ---------------------------------------------------------------------------
// K8: gated RMSNorm: y = (ys * silu(z)); y *= rsqrt(mean(y^2)+1e-5)*norm_g
// warp per row (256 cols), in-place on g_ys.
// ---------------------------------------------------------------------------
__global__ __launch_bounds__(256) void k_gatenorm(const float* __restrict__ ng) {
    int warp = (blockIdx.x * 256 + threadIdx.x) >> 5;
    int lane = threadIdx.x & 31;
    float* yrow = g_ys + (size_t)warp * D_INNER;
    const float* zrow = g_zx + (size_t)warp * D_INPROJ;
    float v[8];
    float ss = 0.0f;
#pragma unroll
    for (int j = 0; j < 8; j++) {
        int e = lane + j * 32;
        float z = zrow[e];
        float gv = yrow[e] * (z / (1.0f + expf(-z)));
        v[j] = gv;
        ss += gv * gv;
    }
#pragma unroll
    for (int o = 16; o > 0; o >>= 1) ss += __shfl_xor_sync(0xffffffffu, ss, o);
    float sc = rsqrtf(ss * (1.0f / 256.0f) + 1e-5f);
#pragma unroll
    for (int j = 0; j < 8; j++) {
        int e = lane + j * 32;
        yrow[e] = v[j] * sc * __ldg(ng + e);
    }
}

// ---------------------------------------------------------------------------
// K10: (m, c) -> NCHW out_2d
// ---------------------------------------------------------------------------
__global__ __launch_bounds__(256) void k_nchw(float* __restrict__ dst) {
    int by = blockIdx.x;                   // b*H + y
    int b = by >> 7, y = by & 127;
    int x0g = blockIdx.y * 64;
    __shared__ float tile[64][129];
    int tid = threadIdx.x;
    int cc = tid & 127;
    for (int xl = tid >> 7; xl < 64; xl += 2)
        tile[xl][cc] = g_buf1[((size_t)by * Ww + x0g + xl) * Cc + cc];
    __syncthreads();
    for (int i = tid; i < 64 * Cc; i += 256) {
        int xl = i & 63;
        int c = i >> 6;
        dst[(((size_t)b * Cc + c) * Hh + y) * Ww + x0g + xl] = tile[xl][c];
    }
}

// ---------------------------------------------------------------------------
extern "C" void kernel_launch(void* const* d_in, const int* in_sizes, int n_in,
                              void* d_out, int out_size) {
    const float* x        = (const float*)d_in[0];
    const float* dw_w     = (const float*)d_in[1];
    const float* gn_g     = (const float*)d_in[2];
    const float* gn_b     = (const float*)d_in[3];
    const float* pw_w     = (const float*)d_in[4];
    const float* pw_b     = (const float*)d_in[5];
    const float* in_projw = (const float*)d_in[6];
    const float* conv_w   = (const float*)d_in[7];
    const float* conv_b   = (const float*)d_in[8];
    const float* dt_bias  = (const float*)d_in[9];
    const float* A_log    = (const float*)d_in[10];
    const float* D_skip   = (const float*)d_in[11];
    const float* norm_g   = (const float*)d_in[12];
    const float* out_w    = (const float*)d_in[13];
    float* out = (float*)d_out;

    float *p_buf1, *p_zx, *p_ys, *p_off;
    cudaGetSymbolAddress((void**)&p_buf1, g_buf1);
    cudaGetSymbolAddress((void**)&p_zx, g_zx);
    cudaGetSymbolAddress((void**)&p_ys, g_ys);
    cudaGetSymbolAddress((void**)&p_off, g_off);

    cudaFuncSetAttribute(k_scan, cudaFuncAttributeMaxDynamicSharedMemorySize, SCAN_SMEM);

    // front-end
    k_dwconv<<<OUT2D_ELEMS / 256, 256>>>(x, dw_w);
    k_gnstats<<<dim3(Bb, 8), 256>>>();
    k_offset<<<OFF_ELEMS / 256, 256>>>(gn_g, gn_b, pw_w, pw_b);
    k_sample<<<dim3(BS, 2), 256>>>(x);

    // in_proj: (M=131072, N=648, K=128)
    k_sgemm<<<dim3((D_INPROJ + 63) / 64, MM / 128), 256>>>(p_buf1, in_projw, p_zx,
                                                           D_INPROJ, 128, D_INPROJ);
    // conv1d + dt
    k_conv1d<<<(MM * D_XBC) / 256, 256>>>(conv_w, conv_b);
    k_dt<<<(MM * NHEADS) / 256, 256>>>(dt_bias);

    // scan
    k_scan<<<dim3(BS, NHEADS), 256, SCAN_SMEM>>>(A_log, D_skip);

    // gated rmsnorm (in place on g_ys)
    k_gatenorm<<<MM / 8, 256>>>(norm_g);

    // out proj: (M=131072, N=128, K=256) -> g_buf1
    k_sgemm<<<dim3(2, MM / 128), 256>>>(p_ys, out_w, p_buf1, 128, 256, 128);

    // NCHW epilogue
    k_nchw<<<dim3(BS, 2), 256>>>(out);

    // offset output (second tuple element), if the buffer holds it
    if (out_size >= OUT2D_ELEMS + OFF_ELEMS)
        cudaMemcpyAsync(out + OUT2D_ELEMS, p_off, OFF_ELEMS * sizeof(float),
                        cudaMemcpyDeviceToDevice);
}

// round 6
// speedup vs baseline: 1.0162x; 1.0162x over previous
#include <cuda_runtime.h>
#include <cuda_bf16.h>
#include <math.h>

// ---------------------------------------------------------------------------
// SnakeScanBranch: dwconv5x5 -> groupnorm+gelu -> pointwise -> offset ->
// grid_sample (y-only deform) -> seq -> in_proj GEMM -> conv1d+silu ->
// selective scan -> gated RMSNorm -> out GEMM -> NCHW.
// R5: both GEMMs moved to tensor pipe via tf32x3 mma.sync (near-fp32 accuracy).
// ---------------------------------------------------------------------------

#define Bb 8
#define Cc 128
#define Hh 128
#define Ww 128
#define HW 16384           // Hh*Ww
#define D_INNER 256
#define D_STATE 64
#define HEADDIM 32
#define NHEADS 8
#define D_XBC 384
#define D_INPROJ 648
#define BS 1024            // Bb*Hh sequences
#define LL 128             // Ww
#define MM 131072          // BS*LL
#define OUT2D_ELEMS 16777216
#define OFF_ELEMS 131072
#define IPW_ELEMS (D_INPROJ * 128)   // 82944
#define OW_ELEMS  (128 * D_INNER)    // 32768

// ---- scratch (device globals; no allocation at runtime) -------------------
__device__ float g_buf1[OUT2D_ELEMS];           // tmp1 -> seq -> out_gemm (reused)
__device__ float g_zx[(size_t)MM * D_INPROJ];
__device__ float g_xbcc[(size_t)MM * D_XBC];
__device__ float g_dt[MM * NHEADS];
__device__ float g_ys[(size_t)MM * D_INNER];
__device__ float g_off[OFF_ELEMS];
__device__ float g_stats[Bb * 8 * 2];
__device__ float g_iphi[IPW_ELEMS];
__device__ float g_iplo[IPW_ELEMS];
__device__ float g_owhi[OW_ELEMS];
__device__ float g_owlo[OW_ELEMS];

// ---------------------------------------------------------------------------
// K1: depthwise 5x5 conv, SAME zero padding
// ---------------------------------------------------------------------------
__global__ __launch_bounds__(256) void k_dwconv(const float* __restrict__ x,
                                                const float* __restrict__ w) {
    int idx = blockIdx.x * 256 + threadIdx.x;
    int xx = idx & 127;
    int yy = (idx >> 7) & 127;
    int c  = (idx >> 14) & 127;
    const float* wp = w + c * 25;
    const float* plane = x + (idx - yy * Ww - xx);
    float acc = 0.0f;
#pragma unroll
    for (int ky = 0; ky < 5; ky++) {
        int sy = yy + ky - 2;
        if (sy < 0 || sy > 127) continue;
        const float* row = plane + sy * Ww;
#pragma unroll
        for (int kx = 0; kx < 5; kx++) {
            int sx = xx + kx - 2;
            if (sx < 0 || sx > 127) continue;
            acc += __ldg(row + sx) * __ldg(wp + ky * 5 + kx);
        }
    }
    g_buf1[idx] = acc;
}

// ---------------------------------------------------------------------------
// K2: groupnorm stats per (b, group)
// ---------------------------------------------------------------------------
__global__ __launch_bounds__(256) void k_gnstats() {
    int b = blockIdx.x, g = blockIdx.y;
    const float* p = g_buf1 + ((size_t)b * Cc + g * 16) * HW;
    float s = 0.0f, ss = 0.0f;
    for (int i = threadIdx.x; i < 16 * HW; i += 256) {
        float v = p[i];
        s += v; ss += v * v;
    }
    __shared__ float rs[256], rss[256];
    rs[threadIdx.x] = s; rss[threadIdx.x] = ss;
    __syncthreads();
    for (int o = 128; o > 0; o >>= 1) {
        if (threadIdx.x < o) { rs[threadIdx.x] += rs[threadIdx.x + o]; rss[threadIdx.x] += rss[threadIdx.x + o]; }
        __syncthreads();
    }
    if (threadIdx.x == 0) {
        const float inv = 1.0f / (16.0f * HW);
        float mean = rs[0] * inv;
        float var  = rss[0] * inv - mean * mean;
        g_stats[(b * 8 + g) * 2]     = mean;
        g_stats[(b * 8 + g) * 2 + 1] = rsqrtf(var + 1e-5f);
    }
}

// ---------------------------------------------------------------------------
// K3: gelu(groupnorm) -> pointwise conv (C->1) -> tanh*8 offset
// ---------------------------------------------------------------------------
__global__ __launch_bounds__(256) void k_offset(const float* __restrict__ gn_g,
                                                const float* __restrict__ gn_b,
                                                const float* __restrict__ pw_w,
                                                const float* __restrict__ pw_b) {
    int idx = blockIdx.x * 256 + threadIdx.x;
    int b = idx >> 14;
    int pix = idx & 16383;
    float acc = 0.0f;
    for (int c = 0; c < Cc; c++) {
        float v = g_buf1[((size_t)b * Cc + c) * HW + pix];
        int grp = c >> 4;
        float mean = __ldg(&g_stats[(b * 8 + grp) * 2]);
        float rstd = __ldg(&g_stats[(b * 8 + grp) * 2 + 1]);
        float u = (v - mean) * rstd * __ldg(gn_g + c) + __ldg(gn_b + c);
        float ge = 0.5f * u * (1.0f + erff(u * 0.70710678118654752440f));
        acc += __ldg(pw_w + c) * ge;
    }
    acc += __ldg(pw_b);
    g_off[idx] = tanhf(acc) * 8.0f;
}

// ---------------------------------------------------------------------------
// K4: grid sample (bilinear, border) + transpose to seq
// ---------------------------------------------------------------------------
__global__ __launch_bounds__(256) void k_sample(const float* __restrict__ x) {
    int by = blockIdx.x;                   // b*H + y
    int b = by >> 7, y = by & 127;
    int x0g = blockIdx.y * 64;
    __shared__ float tile[64][129];
    __shared__ int s_y0[64], s_y1[64], s_x0[64], s_x1[64];
    __shared__ float s_wx[64], s_wy[64];
    int tid = threadIdx.x;
    if (tid < 64) {
        int xg = x0g + tid;
        float off_n = g_off[by * Ww + xg] * (2.0f / 127.0f);
        float byv = -1.0f + y  * (2.0f / 127.0f);
        float bxv = -1.0f + xg * (2.0f / 127.0f);
        float gyv = fminf(fmaxf(byv + off_n, -1.0f), 1.0f);
        float gx = fminf(fmaxf((bxv + 1.0f) * 0.5f * 127.0f, 0.0f), 127.0f);
        float gy = fminf(fmaxf((gyv + 1.0f) * 0.5f * 127.0f, 0.0f), 127.0f);
        float fx0 = floorf(gx), fy0 = floorf(gy);
        s_wx[tid] = gx - fx0;
        s_wy[tid] = gy - fy0;
        int x0i = (int)fx0, y0i = (int)fy0;
        s_x0[tid] = x0i; s_y0[tid] = y0i;
        s_x1[tid] = min(x0i + 1, 127);
        s_y1[tid] = min(y0i + 1, 127);
    }
    __syncthreads();
    for (int i = tid; i < 64 * Cc; i += 256) {
        int xl = i & 63;
        int c = i >> 6;
        const float* pl = x + ((size_t)b * Cc + c) * HW;
        float wx = s_wx[xl], wy = s_wy[xl];
        int r0 = s_y0[xl] * Ww, r1 = s_y1[xl] * Ww;
        float v00 = __ldg(pl + r0 + s_x0[xl]);
        float v01 = __ldg(pl + r0 + s_x1[xl]);
        float v10 = __ldg(pl + r1 + s_x0[xl]);
        float v11 = __ldg(pl + r1 + s_x1[xl]);
        float top = v00 * (1.0f - wx) + v01 * wx;
        float bot = v10 * (1.0f - wx) + v11 * wx;
        tile[xl][c] = top * (1.0f - wy) + bot * wy;
    }
    __syncthreads();
    int cc = tid & 127;
    for (int xl = tid >> 7; xl < 64; xl += 2)
        g_buf1[((size_t)by * Ww + x0g + xl) * Cc + cc] = tile[xl][cc];
}

// ---------------------------------------------------------------------------
// Weight split: w -> tf32 hi + tf32 lo (exact residual split)
// ---------------------------------------------------------------------------
__global__ __launch_bounds__(256) void k_split(const float* __restrict__ w,
                                               float* __restrict__ hi,
                                               float* __restrict__ lo, int n) {
    int i = blockIdx.x * 256 + threadIdx.x;
    if (i >= n) return;
    float v = w[i], h, l2;
    asm("cvt.rna.tf32.f32 %0, %1;" : "=f"(h) : "f"(v));
    float l = v - h;
    asm("cvt.rna.tf32.f32 %0, %1;" : "=f"(l2) : "f"(l));
    hi[i] = h; lo[i] = l2;
}

// ---------------------------------------------------------------------------
// tf32x3 GEMM on tensor pipe: C[m,n] = sum_k A[m,k]*B[n,k]
// BM=128 BN=64 BK=32; 8 warps (4x2); warp tile 32x32; mma m16n8k8.
// A split hi/lo in registers; B pre-split (Bhi/Blo).
// Smem [m][36]/[n][36]: fragment LDS bank pattern = (4g+t) -> conflict-free.
// ---------------------------------------------------------------------------
#define MMA_TF32(d, a, b)                                                     \
    asm volatile(                                                             \
        "mma.sync.aligned.m16n8k8.row.col.f32.tf32.tf32.f32 "                 \
        "{%0,%1,%2,%3}, {%4,%5,%6,%7}, {%8,%9}, {%0,%1,%2,%3};"               \
        : "+f"(d[0]), "+f"(d[1]), "+f"(d[2]), "+f"(d[3])                      \
        : "r"(a[0]), "r"(a[1]), "r"(a[2]), "r"(a[3]), "r"(b[0]), "r"(b[1]))

__global__ __launch_bounds__(256) void k_gemm_tf32(const float* __restrict__ A,
                                                   const float* __restrict__ Bhi,
                                                   const float* __restrict__ Blo,
                                                   float* __restrict__ Cm,
                                                   int N, int K, int ldc) {
    __shared__ float As[128][36];
    __shared__ float Bhs[64][36];
    __shared__ float Bls[64][36];
    int tid = threadIdx.x;
    int lane = tid & 31;
    int wid = tid >> 5;
    int warp_m = (wid >> 1) * 32;
    int warp_n = (wid & 1) * 32;
    int g = lane >> 2;          // 0..7
    int t = lane & 3;           // 0..3
    int m0 = blockIdx.y * 128;
    int n0 = blockIdx.x * 64;

    float acc[2][4][4];
#pragma unroll
    for (int mi = 0; mi < 2; mi++)
#pragma unroll
        for (int ni = 0; ni < 4; ni++)
#pragma unroll
            for (int j = 0; j < 4; j++) acc[mi][ni][j] = 0.0f;

    // global load mappings
    int a_row  = tid >> 1;               // 0..127
    int a_koff = (tid & 1) * 16;         // 0 or 16 (4 float4)
    int b_row  = tid >> 2;               // 0..63
    int b_koff = (tid & 3) * 8;          // 0..24 (2 float4)
    const float* Ag  = A + (size_t)(m0 + a_row) * K + a_koff;
    bool bval = (n0 + b_row) < N;
    const float* Bhg = Bhi + (size_t)(n0 + b_row) * K + b_koff;
    const float* Blg = Blo + (size_t)(n0 + b_row) * K + b_koff;

    float4 ra[4], rbh[2], rbl[2];
    const float4 z4 = make_float4(0.f, 0.f, 0.f, 0.f);

    // prefetch chunk 0
#pragma unroll
    for (int j = 0; j < 4; j++) ra[j] = *(const float4*)(Ag + j * 4);
#pragma unroll
    for (int j = 0; j < 2; j++) {
        rbh[j] = bval ? *(const float4*)(Bhg + j * 4) : z4;
        rbl[j] = bval ? *(const float4*)(Blg + j * 4) : z4;
    }

    int nchunks = K >> 5;
    for (int c = 0; c < nchunks; c++) {
        __syncthreads();
#pragma unroll
        for (int j = 0; j < 4; j++)
            *(float4*)&As[a_row][a_koff + j * 4] = ra[j];
#pragma unroll
        for (int j = 0; j < 2; j++) {
            *(float4*)&Bhs[b_row][b_koff + j * 4] = rbh[j];
            *(float4*)&Bls[b_row][b_koff + j * 4] = rbl[j];
        }
        __syncthreads();
        if (c + 1 < nchunks) {
            int kk = (c + 1) * 32;
#pragma unroll
            for (int j = 0; j < 4; j++) ra[j] = *(const float4*)(Ag + kk + j * 4);
#pragma unroll
            for (int j = 0; j < 2; j++) {
                rbh[j] = bval ? *(const float4*)(Bhg + kk + j * 4) : z4;
                rbl[j] = bval ? *(const float4*)(Blg + kk + j * 4) : z4;
            }
        }
#pragma unroll
        for (int ks = 0; ks < 4; ks++) {
            int kb = ks * 8;
            unsigned ahi[2][4], alo[2][4];
#pragma unroll
            for (int mi = 0; mi < 2; mi++) {
                int rm = warp_m + mi * 16;
                float av[4];
                av[0] = As[rm + g][kb + t];
                av[1] = As[rm + g + 8][kb + t];
                av[2] = As[rm + g][kb + t + 4];
                av[3] = As[rm + g + 8][kb + t + 4];
#pragma unroll
                for (int j = 0; j < 4; j++) {
                    float h, l2;
                    asm("cvt.rna.tf32.f32 %0, %1;" : "=f"(h) : "f"(av[j]));
                    float l = av[j] - h;
                    asm("cvt.rna.tf32.f32 %0, %1;" : "=f"(l2) : "f"(l));
                    ahi[mi][j] = __float_as_uint(h);
                    alo[mi][j] = __float_as_uint(l2);
                }
            }
            unsigned bh[4][2], bl[4][2];
#pragma unroll
            for (int ni = 0; ni < 4; ni++) {
                int cn = warp_n + ni * 8;
                bh[ni][0] = __float_as_uint(Bhs[cn + g][kb + t]);
                bh[ni][1] = __float_as_uint(Bhs[cn + g][kb + t + 4]);
                bl[ni][0] = __float_as_uint(Bls[cn + g][kb + t]);
                bl[ni][1] = __float_as_uint(Bls[cn + g][kb + t + 4]);
            }
#pragma unroll
            for (int mi = 0; mi < 2; mi++)
#pragma unroll
                for (int ni = 0; ni < 4; ni++) {
                    MMA_TF32(acc[mi][ni], ahi[mi], bh[ni]);
                    MMA_TF32(acc[mi][ni], ahi[mi], bl[ni]);
                    MMA_TF32(acc[mi][ni], alo[mi], bh[ni]);
                }
        }
    }

    // epilogue
#pragma unroll
    for (int mi = 0; mi < 2; mi++) {
        int r0 = m0 + warp_m + mi * 16 + g;
#pragma unroll
        for (int ni = 0; ni < 4; ni++) {
            int col = n0 + warp_n + ni * 8 + t * 2;
            if (col + 1 < N) {
                *(float2*)(Cm + (size_t)r0 * ldc + col) =
                    make_float2(acc[mi][ni][0], acc[mi][ni][1]);
                *(float2*)(Cm + (size_t)(r0 + 8) * ldc + col) =
                    make_float2(acc[mi][ni][2], acc[mi][ni][3]);
            } else if (col < N) {
                Cm[(size_t)r0 * ldc + col] = acc[mi][ni][0];
                Cm[(size_t)(r0 + 8) * ldc + col] = acc[mi][ni][2];
            }
        }
    }
}

// ---------------------------------------------------------------------------
// K6: causal depthwise conv1d (4 taps) + bias + silu
// ---------------------------------------------------------------------------
__global__ __launch_bounds__(256) void k_conv1d(const float* __restrict__ cw,
                                                const float* __restrict__ cb) {
    int idx = blockIdx.x * 256 + threadIdx.x;
    int e = idx % D_XBC;
    int ml = idx / D_XBC;
    int l = ml & 127;
    int bs = ml >> 7;
    const float* src = g_zx + ((size_t)bs * LL) * D_INPROJ + D_INNER + e;
    float4 w = *(const float4*)(cw + e * 4);
    float acc = __ldg(cb + e);
    const float wt[4] = {w.x, w.y, w.z, w.w};
#pragma unroll
    for (int k = 0; k < 4; k++) {
        int lp = l - 3 + k;
        if (lp >= 0) acc += wt[k] * src[(size_t)lp * D_INPROJ];
    }
    g_xbcc[idx] = acc / (1.0f + expf(-acc));
}

// K6b: dt = softplus(raw + dt_bias)
__global__ __launch_bounds__(256) void k_dt(const float* __restrict__ dt_bias) {
    int idx = blockIdx.x * 256 + threadIdx.x;
    int h = idx & 7;
    int m = idx >> 3;
    float v = g_zx[(size_t)m * D_INPROJ + 640 + h] + __ldg(dt_bias + h);
    g_dt[idx] = fmaxf(v, 0.0f) + log1pf(expf(-fabsf(v)));
}

// ---------------------------------------------------------------------------
// K7: selective scan. Block per (seq, head).
// ---------------------------------------------------------------------------
#define SCAN_SMEM ((8192 + 8192 + 4096 + 128 + 128) * 4)
__global__ __launch_bounds__(256) void k_scan(const float* __restrict__ A_log,
                                              const float* __restrict__ Dskip) {
    extern __shared__ float sm[];
    float* sB  = sm;
    float* sC  = sB + 8192;
    float* sx  = sC + 8192;
    float* sdt = sx + 4096;
    float* sdA = sdt + 128;
    int bs = blockIdx.x, hh = blockIdx.y;
    int tid = threadIdx.x;
    float Ah = -expf(__ldg(A_log + hh));
    float Dh = __ldg(Dskip + hh);

    const float* base = g_xbcc + (size_t)bs * LL * D_XBC;
    for (int i = tid; i < 128 * 64; i += 256) {
        int l = i >> 6, s = i & 63;
        sB[i] = base[l * D_XBC + D_INNER + s];
        sC[i] = base[l * D_XBC + D_INNER + D_STATE + s];
    }
    for (int i = tid; i < 128 * 32; i += 256) {
        int l = i >> 5, d = i & 31;
        sx[i] = base[l * D_XBC + hh * HEADDIM + d];
    }
    if (tid < 128) {
        float v = g_dt[((size_t)bs * LL + tid) * NHEADS + hh];
        sdt[tid] = v;
        sdA[tid] = expf(v * Ah);
    }
    __syncthreads();

    int d = tid >> 3;
    int s8 = tid & 7;
    int sb = s8 * 8;
    float h[8] = {0, 0, 0, 0, 0, 0, 0, 0};
    float* ysout = g_ys + ((size_t)bs * LL) * D_INNER + hh * HEADDIM + d;

    for (int l = 0; l < LL; l++) {
        float dtv = sdt[l];
        float dA = sdA[l];
        float xv = sx[l * 32 + d];
        float cf = dtv * xv;
        float4 b0 = *(const float4*)&sB[l * 64 + sb];
        float4 b1 = *(const float4*)&sB[l * 64 + sb + 4];
        float4 c0 = *(const float4*)&sC[l * 64 + sb];
        float4 c1 = *(const float4*)&sC[l * 64 + sb + 4];
        float y = 0.0f;
        h[0] = h[0] * dA + cf * b0.x; y += h[0] * c0.x;
        h[1] = h[1] * dA + cf * b0.y; y += h[1] * c0.y;
        h[2] = h[2] * dA + cf * b0.z; y += h[2] * c0.z;
        h[3] = h[3] * dA + cf * b0.w; y += h[3] * c0.w;
        h[4] = h[4] * dA + cf * b1.x; y += h[4] * c1.x;
        h[5] = h[5] * dA + cf * b1.y; y += h[5] * c1.y;
        h[6] = h[6] * dA + cf * b1.z; y += h[6] * c1.z;
        h[7] = h[7] * dA + cf * b1.w; y += h[7] * c1.w;
        y += __shfl_down_sync(0xffffffffu, y, 4, 8);
        y += __shfl_down_sync(0xffffffffu, y, 2, 8);
        y += __shfl_down_sync(0xffffffffu, y, 1, 8);
        if (s8 == 0) ysout[(size_t)l * D_INNER] = y + Dh * xv;
    }
}

// ---------------------------------------------------------------------------
// K8: gated RMSNorm (in place on g_ys)
// ---------------------------------------------------------------------------
__global__ __launch_bounds__(256) void k_gatenorm(const float* __restrict__ ng) {
    int warp = (blockIdx.x * 256 + threadIdx.x) >> 5;
    int lane = threadIdx.x & 31;
    float* yrow = g_ys + (size_t)warp * D_INNER;
    const float* zrow = g_zx + (size_t)warp * D_INPROJ;
    float v[8];
    float ss = 0.0f;
#pragma unroll
    for (int j = 0; j < 8; j++) {
        int e = lane + j * 32;
        float z = zrow[e];
        float gv = yrow[e] * (z / (1.0f + expf(-z)));
        v[j] = gv;
        ss += gv * gv;
    }
#pragma unroll
    for (int o = 16; o > 0; o >>= 1) ss += __shfl_xor_sync(0xffffffffu, ss, o);
    float sc = rsqrtf(ss * (1.0f / 256.0f) + 1e-5f);
#pragma unroll
    for (int j = 0; j < 8; j++) {
        int e = lane + j * 32;
        yrow[e] = v[j] * sc * __ldg(ng + e);
    }
}

// ---------------------------------------------------------------------------
// K10: (m, c) -> NCHW out_2d
// ---------------------------------------------------------------------------
__global__ __launch_bounds__(256) void k_nchw(float* __restrict__ dst) {
    int by = blockIdx.x;
    int b = by >> 7, y = by & 127;
    int x0g = blockIdx.y * 64;
    __shared__ float tile[64][129];
    int tid = threadIdx.x;
    int cc = tid & 127;
    for (int xl = tid >> 7; xl < 64; xl += 2)
        tile[xl][cc] = g_buf1[((size_t)by * Ww + x0g + xl) * Cc + cc];
    __syncthreads();
    for (int i = tid; i < 64 * Cc; i += 256) {
        int xl = i & 63;
        int c = i >> 6;
        dst[(((size_t)b * Cc + c) * Hh + y) * Ww + x0g + xl] = tile[xl][c];
    }
}

// ---------------------------------------------------------------------------
extern "C" void kernel_launch(void* const* d_in, const int* in_sizes, int n_in,
                              void* d_out, int out_size) {
    const float* x        = (const float*)d_in[0];
    const float* dw_w     = (const float*)d_in[1];
    const float* gn_g     = (const float*)d_in[2];
    const float* gn_b     = (const float*)d_in[3];
    const float* pw_w     = (const float*)d_in[4];
    const float* pw_b     = (const float*)d_in[5];
    const float* in_projw = (const float*)d_in[6];
    const float* conv_w   = (const float*)d_in[7];
    const float* conv_b   = (const float*)d_in[8];
    const float* dt_bias  = (const float*)d_in[9];
    const float* A_log    = (const float*)d_in[10];
    const float* D_skip   = (const float*)d_in[11];
    const float* norm_g   = (const float*)d_in[12];
    const float* out_w    = (const float*)d_in[13];
    float* out = (float*)d_out;

    float *p_buf1, *p_zx, *p_ys, *p_off, *p_iphi, *p_iplo, *p_owhi, *p_owlo;
    cudaGetSymbolAddress((void**)&p_buf1, g_buf1);
    cudaGetSymbolAddress((void**)&p_zx, g_zx);
    cudaGetSymbolAddress((void**)&p_ys, g_ys);
    cudaGetSymbolAddress((void**)&p_off, g_off);
    cudaGetSymbolAddress((void**)&p_iphi, g_iphi);
    cudaGetSymbolAddress((void**)&p_iplo, g_iplo);
    cudaGetSymbolAddress((void**)&p_owhi, g_owhi);
    cudaGetSymbolAddress((void**)&p_owlo, g_owlo);

    cudaFuncSetAttribute(k_scan, cudaFuncAttributeMaxDynamicSharedMemorySize, SCAN_SMEM);

    // weight splits (tiny)
    k_split<<<(IPW_ELEMS + 255) / 256, 256>>>(in_projw, p_iphi, p_iplo, IPW_ELEMS);
    k_split<<<(OW_ELEMS + 255) / 256, 256>>>(out_w, p_owhi, p_owlo, OW_ELEMS);

    // front-end
    k_dwconv<<<OUT2D_ELEMS / 256, 256>>>(x, dw_w);
    k_gnstats<<<dim3(Bb, 8), 256>>>();
    k_offset<<<OFF_ELEMS / 256, 256>>>(gn_g, gn_b, pw_w, pw_b);
    k_sample<<<dim3(BS, 2), 256>>>(x);

    // in_proj: (M=131072, N=648, K=128) on tensor pipe
    k_gemm_tf32<<<dim3((D_INPROJ + 63) / 64, MM / 128), 256>>>(
        p_buf1, p_iphi, p_iplo, p_zx, D_INPROJ, 128, D_INPROJ);

    // conv1d + dt
    k_conv1d<<<(MM * D_XBC) / 256, 256>>>(conv_w, conv_b);
    k_dt<<<(MM * NHEADS) / 256, 256>>>(dt_bias);

    // scan
    k_scan<<<dim3(BS, NHEADS), 256, SCAN_SMEM>>>(A_log, D_skip);

    // gated rmsnorm
    k_gatenorm<<<MM / 8, 256>>>(norm_g);

    // out proj: (M=131072, N=128, K=256) on tensor pipe -> g_buf1
    k_gemm_tf32<<<dim3(2, MM / 128), 256>>>(p_ys, p_owhi, p_owlo, p_buf1,
                                            128, 256, 128);

    // NCHW epilogue
    k_nchw<<<dim3(BS, 2), 256>>>(out);

    if (out_size >= OUT2D_ELEMS + OFF_ELEMS)
        cudaMemcpyAsync(out + OUT2D_ELEMS, p_off, OFF_ELEMS * sizeof(float),
                        cudaMemcpyDeviceToDevice);
}

// round 8
// speedup vs baseline: 1.1316x; 1.1135x over previous
#include <cuda_runtime.h>
#include <cuda_bf16.h>
#include <math.h>
#include <stdint.h>

// ---------------------------------------------------------------------------
// SnakeScanBranch R7: GEMMs via legacy bf16 mma.sync m16n8k16 + ldmatrix,
// 3-product bf16 split (hi/lo) for near-fp32 accuracy, fp32 accumulate.
// All conversions hoisted to producers; GEMM inner loop = LDSM + HMMA only.
// ---------------------------------------------------------------------------

#define Bb 8
#define Cc 128
#define Hh 128
#define Ww 128
#define HW 16384
#define D_INNER 256
#define D_STATE 64
#define HEADDIM 32
#define NHEADS 8
#define D_XBC 384
#define D_INPROJ 648
#define BS 1024
#define LL 128
#define MM 131072
#define OUT2D_ELEMS 16777216
#define OFF_ELEMS 131072
#define IPW_ELEMS (D_INPROJ * 128)   // 82944
#define OW_ELEMS  (128 * D_INNER)    // 32768

// ---- scratch (device globals) ---------------------------------------------
__device__ float g_buf1[OUT2D_ELEMS];          // dwconv tmp -> out-gemm result
__device__ float g_zx[(size_t)MM * D_INPROJ];
__device__ float g_xbcc[(size_t)MM * D_XBC];
__device__ float g_dt[MM * NHEADS];
__device__ float g_ys[(size_t)MM * D_INNER];
__device__ float g_off[OFF_ELEMS];
__device__ float g_stats[Bb * 8 * 2];
// bf16 split activations / weights (uint4 for 16B-aligned vector access)
__device__ uint4 g_seq_hi[(size_t)MM * 128 / 8];
__device__ uint4 g_seq_lo[(size_t)MM * 128 / 8];
__device__ uint4 g_y_hi[(size_t)MM * 256 / 8];
__device__ uint4 g_y_lo[(size_t)MM * 256 / 8];
__device__ uint4 g_ipw_hi[IPW_ELEMS / 8];
__device__ uint4 g_ipw_lo[IPW_ELEMS / 8];
__device__ uint4 g_ow_hi[OW_ELEMS / 8];
__device__ uint4 g_ow_lo[OW_ELEMS / 8];

// ---------------------------------------------------------------------------
__device__ __forceinline__ uint32_t smem_u32(const void* p) {
    uint32_t a;
    asm("{ .reg .u64 t; cvta.to.shared.u64 t, %1; cvt.u32.u64 %0, t; }"
        : "=r"(a) : "l"(p));
    return a;
}

#define LDSM4(r, addr)                                                        \
    asm volatile("ldmatrix.sync.aligned.m8n8.x4.shared.b16 {%0,%1,%2,%3}, [%4];" \
                 : "=r"((r)[0]), "=r"((r)[1]), "=r"((r)[2]), "=r"((r)[3])     \
                 : "r"(addr))

#define MMA_BF16(d, a, b0, b1)                                                \
    asm volatile(                                                             \
        "mma.sync.aligned.m16n8k16.row.col.f32.bf16.bf16.f32 "                \
        "{%0,%1,%2,%3}, {%4,%5,%6,%7}, {%8,%9}, {%0,%1,%2,%3};"               \
        : "+f"((d)[0]), "+f"((d)[1]), "+f"((d)[2]), "+f"((d)[3])              \
        : "r"((a)[0]), "r"((a)[1]), "r"((a)[2]), "r"((a)[3]), "r"(b0), "r"(b1))

__device__ __forceinline__ uint32_t bf16_hi_pack(float a, float b,
                                                 uint32_t& lo_out) {
    __nv_bfloat16 h0 = __float2bfloat16(a);
    __nv_bfloat16 h1 = __float2bfloat16(b);
    __nv_bfloat16 l0 = __float2bfloat16(a - __bfloat162float(h0));
    __nv_bfloat16 l1 = __float2bfloat16(b - __bfloat162float(h1));
    lo_out = ((uint32_t)__bfloat16_as_ushort(l1) << 16) | __bfloat16_as_ushort(l0);
    return ((uint32_t)__bfloat16_as_ushort(h1) << 16) | __bfloat16_as_ushort(h0);
}

// ---------------------------------------------------------------------------
// K1: depthwise 5x5 conv
// ---------------------------------------------------------------------------
__global__ __launch_bounds__(256) void k_dwconv(const float* __restrict__ x,
                                                const float* __restrict__ w) {
    int idx = blockIdx.x * 256 + threadIdx.x;
    int xx = idx & 127;
    int yy = (idx >> 7) & 127;
    int c  = (idx >> 14) & 127;
    const float* wp = w + c * 25;
    const float* plane = x + (idx - yy * Ww - xx);
    float acc = 0.0f;
#pragma unroll
    for (int ky = 0; ky < 5; ky++) {
        int sy = yy + ky - 2;
        if (sy < 0 || sy > 127) continue;
        const float* row = plane + sy * Ww;
#pragma unroll
        for (int kx = 0; kx < 5; kx++) {
            int sx = xx + kx - 2;
            if (sx < 0 || sx > 127) continue;
            acc += __ldg(row + sx) * __ldg(wp + ky * 5 + kx);
        }
    }
    g_buf1[idx] = acc;
}

// ---------------------------------------------------------------------------
// K2: groupnorm stats
// ---------------------------------------------------------------------------
__global__ __launch_bounds__(256) void k_gnstats() {
    int b = blockIdx.x, g = blockIdx.y;
    const float* p = g_buf1 + ((size_t)b * Cc + g * 16) * HW;
    float s = 0.0f, ss = 0.0f;
    for (int i = threadIdx.x; i < 16 * HW; i += 256) {
        float v = p[i];
        s += v; ss += v * v;
    }
    __shared__ float rs[256], rss[256];
    rs[threadIdx.x] = s; rss[threadIdx.x] = ss;
    __syncthreads();
    for (int o = 128; o > 0; o >>= 1) {
        if (threadIdx.x < o) { rs[threadIdx.x] += rs[threadIdx.x + o]; rss[threadIdx.x] += rss[threadIdx.x + o]; }
        __syncthreads();
    }
    if (threadIdx.x == 0) {
        const float inv = 1.0f / (16.0f * HW);
        float mean = rs[0] * inv;
        float var  = rss[0] * inv - mean * mean;
        g_stats[(b * 8 + g) * 2]     = mean;
        g_stats[(b * 8 + g) * 2 + 1] = rsqrtf(var + 1e-5f);
    }
}

// ---------------------------------------------------------------------------
// K3: gelu(gn) -> pointwise -> tanh*8
// ---------------------------------------------------------------------------
__global__ __launch_bounds__(256) void k_offset(const float* __restrict__ gn_g,
                                                const float* __restrict__ gn_b,
                                                const float* __restrict__ pw_w,
                                                const float* __restrict__ pw_b) {
    int idx = blockIdx.x * 256 + threadIdx.x;
    int b = idx >> 14;
    int pix = idx & 16383;
    float acc = 0.0f;
    for (int c = 0; c < Cc; c++) {
        float v = g_buf1[((size_t)b * Cc + c) * HW + pix];
        int grp = c >> 4;
        float mean = __ldg(&g_stats[(b * 8 + grp) * 2]);
        float rstd = __ldg(&g_stats[(b * 8 + grp) * 2 + 1]);
        float u = (v - mean) * rstd * __ldg(gn_g + c) + __ldg(gn_b + c);
        float ge = 0.5f * u * (1.0f + erff(u * 0.70710678118654752440f));
        acc += __ldg(pw_w + c) * ge;
    }
    acc += __ldg(pw_b);
    g_off[idx] = tanhf(acc) * 8.0f;
}

// ---------------------------------------------------------------------------
// K4: grid sample (bilinear, border) -> seq, emitted as bf16 hi/lo
// ---------------------------------------------------------------------------
__global__ __launch_bounds__(256) void k_sample(const float* __restrict__ x) {
    int by = blockIdx.x;                   // b*H + y
    int b = by >> 7, y = by & 127;
    int x0g = blockIdx.y * 64;
    __shared__ float tile[64][129];
    __shared__ int s_y0[64], s_y1[64], s_x0[64], s_x1[64];
    __shared__ float s_wx[64], s_wy[64];
    int tid = threadIdx.x;
    if (tid < 64) {
        int xg = x0g + tid;
        float off_n = g_off[by * Ww + xg] * (2.0f / 127.0f);
        float byv = -1.0f + y  * (2.0f / 127.0f);
        float bxv = -1.0f + xg * (2.0f / 127.0f);
        float gyv = fminf(fmaxf(byv + off_n, -1.0f), 1.0f);
        float gx = fminf(fmaxf((bxv + 1.0f) * 0.5f * 127.0f, 0.0f), 127.0f);
        float gy = fminf(fmaxf((gyv + 1.0f) * 0.5f * 127.0f, 0.0f), 127.0f);
        float fx0 = floorf(gx), fy0 = floorf(gy);
        s_wx[tid] = gx - fx0;
        s_wy[tid] = gy - fy0;
        int x0i = (int)fx0, y0i = (int)fy0;
        s_x0[tid] = x0i; s_y0[tid] = y0i;
        s_x1[tid] = min(x0i + 1, 127);
        s_y1[tid] = min(y0i + 1, 127);
    }
    __syncthreads();
    for (int i = tid; i < 64 * Cc; i += 256) {
        int xl = i & 63;
        int c = i >> 6;
        const float* pl = x + ((size_t)b * Cc + c) * HW;
        float wx = s_wx[xl], wy = s_wy[xl];
        int r0 = s_y0[xl] * Ww, r1 = s_y1[xl] * Ww;
        float v00 = __ldg(pl + r0 + s_x0[xl]);
        float v01 = __ldg(pl + r0 + s_x1[xl]);
        float v10 = __ldg(pl + r1 + s_x0[xl]);
        float v11 = __ldg(pl + r1 + s_x1[xl]);
        float top = v00 * (1.0f - wx) + v01 * wx;
        float bot = v10 * (1.0f - wx) + v11 * wx;
        tile[xl][c] = top * (1.0f - wy) + bot * wy;
    }
    __syncthreads();
    // write bf16 hi/lo seq rows: 2 threads per (xl), each 64 channels
    __nv_bfloat16* sh = (__nv_bfloat16*)g_seq_hi;
    __nv_bfloat16* sl = (__nv_bfloat16*)g_seq_lo;
    for (int i = tid; i < 64 * Cc; i += 256) {
        int xl = i >> 7;
        int c0 = (i & 127);
        // regroup: thread handles one element (simple, coalesced over c)
        float v = tile[xl * 2 + (c0 >> 6)][(c0 & 63) | 0];
        // NOTE: remap so consecutive tid covers consecutive c of one row
        int xr = (i >> 7);
        (void)v; (void)xr;
        // simpler exact mapping below
    }
    // exact mapping: i = xl*128 + c
    for (int i = tid; i < 64 * Cc; i += 256) {
        int xl = i >> 7;
        int c = i & 127;
        float v = tile[xl][c];
        __nv_bfloat16 h = __float2bfloat16(v);
        __nv_bfloat16 l = __float2bfloat16(v - __bfloat162float(h));
        size_t o = ((size_t)by * Ww + x0g + xl) * 128 + c;
        sh[o] = h; sl[o] = l;
    }
}

// ---------------------------------------------------------------------------
// Weight split fp32 -> bf16 hi + bf16 lo
// ---------------------------------------------------------------------------
__global__ __launch_bounds__(256) void k_wsplit(const float* __restrict__ w,
                                                uint4* __restrict__ hi4,
                                                uint4* __restrict__ lo4, int n) {
    int i = blockIdx.x * 256 + threadIdx.x;
    if (i >= n) return;
    float v = w[i];
    __nv_bfloat16 h = __float2bfloat16(v);
    __nv_bfloat16 l = __float2bfloat16(v - __bfloat162float(h));
    ((__nv_bfloat16*)hi4)[i] = h;
    ((__nv_bfloat16*)lo4)[i] = l;
}

// ---------------------------------------------------------------------------
// bf16x3 GEMM: C[m,n] = sum_k A[m,k]*B[n,k]
// A, B pre-split bf16 hi/lo. Tile 128x64, chunk K=128. 8 warps (4m x 2n),
// warp tile 32x32: 2 mi x 4 ni of m16n8k16. ldmatrix.x4 fragment loads.
// Smem rows padded to 136 halves -> conflict-free LDSM and stores.
// ---------------------------------------------------------------------------
#define APAD 136
#define SM_AHI 0
#define SM_ALO 34816                 // 128*136*2
#define SM_BHI 69632
#define SM_BLO 87040                 // + 64*136*2
#define SMEM_GEMM 104448

__global__ __launch_bounds__(256) void k_gemm_bf16(const uint4* __restrict__ Ahi,
                                                   const uint4* __restrict__ Alo,
                                                   const uint4* __restrict__ Bhi,
                                                   const uint4* __restrict__ Blo,
                                                   float* __restrict__ Cm,
                                                   int N, int K, int ldc) {
    extern __shared__ char sm[];
    uint32_t smb = smem_u32(sm);
    int tid = threadIdx.x;
    int lane = tid & 31;
    int wid = tid >> 5;
    int wm = (wid >> 1) * 32;
    int wn = (wid & 1) * 32;
    int m0 = blockIdx.y * 128;
    int n0 = blockIdx.x * 64;
    int K8 = K >> 3;

    float acc[2][4][4];
#pragma unroll
    for (int mi = 0; mi < 2; mi++)
#pragma unroll
        for (int ni = 0; ni < 4; ni++)
#pragma unroll
            for (int j = 0; j < 4; j++) acc[mi][ni][j] = 0.0f;

    // ldmatrix per-lane address components (halves)
    int a_r  = lane & 15;
    int a_c8 = (lane >> 4) << 3;
    uint32_t a_base = ((uint32_t)(wm + a_r) * APAD + a_c8) * 2;
    int b_r  = (lane & 7) + ((lane >> 4) << 3);
    int b_c8 = ((lane >> 3) & 1) << 3;
    uint32_t b_base = ((uint32_t)(wn + b_r) * APAD + b_c8) * 2;

    int nchunks = K >> 7;
    for (int ch = 0; ch < nchunks; ch++) {
        if (ch) __syncthreads();
        int kc8 = ch << 4;           // chunk offset in uint4 units (128/8)
        // ---- stage A: 128 rows x 16 groups, hi+lo
#pragma unroll
        for (int it = 0; it < 8; it++) {
            int g = it * 256 + tid;              // 0..2047
            int row = g >> 4, kg = g & 15;
            size_t go = (size_t)(m0 + row) * K8 + kc8 + kg;
            uint32_t so = ((uint32_t)row * APAD + kg * 8) * 2;
            *(uint4*)(sm + SM_AHI + so) = Ahi[go];
            *(uint4*)(sm + SM_ALO + so) = Alo[go];
        }
        // ---- stage B: 64 rows x 16 groups, hi+lo
#pragma unroll
        for (int it = 0; it < 4; it++) {
            int g = it * 256 + tid;              // 0..1023
            int row = g >> 4, kg = g & 15;
            uint4 h = make_uint4(0, 0, 0, 0), l = make_uint4(0, 0, 0, 0);
            if (n0 + row < N) {
                size_t go = (size_t)(n0 + row) * K8 + kc8 + kg;
                h = Bhi[go]; l = Blo[go];
            }
            uint32_t so = ((uint32_t)row * APAD + kg * 8) * 2;
            *(uint4*)(sm + SM_BHI + so) = h;
            *(uint4*)(sm + SM_BLO + so) = l;
        }
        __syncthreads();
        // ---- compute: 8 k16 steps
#pragma unroll
        for (int k16 = 0; k16 < 8; k16++) {
            uint32_t kb2 = (uint32_t)(k16 * 16) * 2;   // byte offset of kb
            uint32_t Ah[2][4], Al[2][4], Bh[2][4], Bl[2][4];
#pragma unroll
            for (int mi = 0; mi < 2; mi++) {
                uint32_t ad = smb + a_base + (uint32_t)mi * (16 * APAD * 2) + kb2;
                LDSM4(Ah[mi], ad + SM_AHI);
                LDSM4(Al[mi], ad + SM_ALO);
            }
#pragma unroll
            for (int nj = 0; nj < 2; nj++) {
                uint32_t bd = smb + b_base + (uint32_t)nj * (16 * APAD * 2) + kb2;
                LDSM4(Bh[nj], bd + SM_BHI);
                LDSM4(Bl[nj], bd + SM_BLO);
            }
#pragma unroll
            for (int mi = 0; mi < 2; mi++)
#pragma unroll
                for (int nj = 0; nj < 2; nj++) {
                    MMA_BF16(acc[mi][2 * nj + 0], Ah[mi], Bh[nj][0], Bh[nj][1]);
                    MMA_BF16(acc[mi][2 * nj + 0], Ah[mi], Bl[nj][0], Bl[nj][1]);
                    MMA_BF16(acc[mi][2 * nj + 0], Al[mi], Bh[nj][0], Bh[nj][1]);
                    MMA_BF16(acc[mi][2 * nj + 1], Ah[mi], Bh[nj][2], Bh[nj][3]);
                    MMA_BF16(acc[mi][2 * nj + 1], Ah[mi], Bl[nj][2], Bl[nj][3]);
                    MMA_BF16(acc[mi][2 * nj + 1], Al[mi], Bh[nj][2], Bh[nj][3]);
                }
        }
    }

    // ---- epilogue
    int g = lane >> 2, t = lane & 3;
#pragma unroll
    for (int mi = 0; mi < 2; mi++) {
        int r0 = m0 + wm + mi * 16 + g;
#pragma unroll
        for (int ni = 0; ni < 4; ni++) {
            int col = n0 + wn + ni * 8 + t * 2;
            if (col + 1 < N) {
                *(float2*)(Cm + (size_t)r0 * ldc + col) =
                    make_float2(acc[mi][ni][0], acc[mi][ni][1]);
                *(float2*)(Cm + (size_t)(r0 + 8) * ldc + col) =
                    make_float2(acc[mi][ni][2], acc[mi][ni][3]);
            } else if (col < N) {
                Cm[(size_t)r0 * ldc + col] = acc[mi][ni][0];
                Cm[(size_t)(r0 + 8) * ldc + col] = acc[mi][ni][2];
            }
        }
    }
}

// ---------------------------------------------------------------------------
// K6: causal depthwise conv1d + bias + silu
// ---------------------------------------------------------------------------
__global__ __launch_bounds__(256) void k_conv1d(const float* __restrict__ cw,
                                                const float* __restrict__ cb) {
    int idx = blockIdx.x * 256 + threadIdx.x;
    int e = idx % D_XBC;
    int ml = idx / D_XBC;
    int l = ml & 127;
    int bs = ml >> 7;
    const float* src = g_zx + ((size_t)bs * LL) * D_INPROJ + D_INNER + e;
    float4 w = *(const float4*)(cw + e * 4);
    float acc = __ldg(cb + e);
    const float wt[4] = {w.x, w.y, w.z, w.w};
#pragma unroll
    for (int k = 0; k < 4; k++) {
        int lp = l - 3 + k;
        if (lp >= 0) acc += wt[k] * src[(size_t)lp * D_INPROJ];
    }
    g_xbcc[idx] = acc / (1.0f + expf(-acc));
}

__global__ __launch_bounds__(256) void k_dt(const float* __restrict__ dt_bias) {
    int idx = blockIdx.x * 256 + threadIdx.x;
    int h = idx & 7;
    int m = idx >> 3;
    float v = g_zx[(size_t)m * D_INPROJ + 640 + h] + __ldg(dt_bias + h);
    g_dt[idx] = fmaxf(v, 0.0f) + log1pf(expf(-fabsf(v)));
}

// ---------------------------------------------------------------------------
// K7: selective scan
// ---------------------------------------------------------------------------
#define SCAN_SMEM ((8192 + 8192 + 4096 + 128 + 128) * 4)
__global__ __launch_bounds__(256) void k_scan(const float* __restrict__ A_log,
                                              const float* __restrict__ Dskip) {
    extern __shared__ float smf[];
    float* sB  = smf;
    float* sC  = sB + 8192;
    float* sx  = sC + 8192;
    float* sdt = sx + 4096;
    float* sdA = sdt + 128;
    int bs = blockIdx.x, hh = blockIdx.y;
    int tid = threadIdx.x;
    float Ah = -expf(__ldg(A_log + hh));
    float Dh = __ldg(Dskip + hh);

    const float* base = g_xbcc + (size_t)bs * LL * D_XBC;
    for (int i = tid; i < 128 * 64; i += 256) {
        int l = i >> 6, s = i & 63;
        sB[i] = base[l * D_XBC + D_INNER + s];
        sC[i] = base[l * D_XBC + D_INNER + D_STATE + s];
    }
    for (int i = tid; i < 128 * 32; i += 256) {
        int l = i >> 5, d = i & 31;
        sx[i] = base[l * D_XBC + hh * HEADDIM + d];
    }
    if (tid < 128) {
        float v = g_dt[((size_t)bs * LL + tid) * NHEADS + hh];
        sdt[tid] = v;
        sdA[tid] = expf(v * Ah);
    }
    __syncthreads();

    int d = tid >> 3;
    int s8 = tid & 7;
    int sb = s8 * 8;
    float h[8] = {0, 0, 0, 0, 0, 0, 0, 0};
    float* ysout = g_ys + ((size_t)bs * LL) * D_INNER + hh * HEADDIM + d;

    for (int l = 0; l < LL; l++) {
        float dtv = sdt[l];
        float dA = sdA[l];
        float xv = sx[l * 32 + d];
        float cf = dtv * xv;
        float4 b0 = *(const float4*)&sB[l * 64 + sb];
        float4 b1 = *(const float4*)&sB[l * 64 + sb + 4];
        float4 c0 = *(const float4*)&sC[l * 64 + sb];
        float4 c1 = *(const float4*)&sC[l * 64 + sb + 4];
        float y = 0.0f;
        h[0] = h[0] * dA + cf * b0.x; y += h[0] * c0.x;
        h[1] = h[1] * dA + cf * b0.y; y += h[1] * c0.y;
        h[2] = h[2] * dA + cf * b0.z; y += h[2] * c0.z;
        h[3] = h[3] * dA + cf * b0.w; y += h[3] * c0.w;
        h[4] = h[4] * dA + cf * b1.x; y += h[4] * c1.x;
        h[5] = h[5] * dA + cf * b1.y; y += h[5] * c1.y;
        h[6] = h[6] * dA + cf * b1.z; y += h[6] * c1.z;
        h[7] = h[7] * dA + cf * b1.w; y += h[7] * c1.w;
        y += __shfl_down_sync(0xffffffffu, y, 4, 8);
        y += __shfl_down_sync(0xffffffffu, y, 2, 8);
        y += __shfl_down_sync(0xffffffffu, y, 1, 8);
        if (s8 == 0) ysout[(size_t)l * D_INNER] = y + Dh * xv;
    }
}

// ---------------------------------------------------------------------------
// K8: gated RMSNorm -> bf16 hi/lo output for out GEMM
// ---------------------------------------------------------------------------
__global__ __launch_bounds__(256) void k_gatenorm(const float* __restrict__ ng) {
    int warp = (blockIdx.x * 256 + threadIdx.x) >> 5;
    int lane = threadIdx.x & 31;
    const float* yrow = g_ys + (size_t)warp * D_INNER;
    const float* zrow = g_zx + (size_t)warp * D_INPROJ;
    float v[8];
    float ss = 0.0f;
#pragma unroll
    for (int j = 0; j < 8; j++) {
        int e = lane + j * 32;
        float z = zrow[e];
        float gv = yrow[e] * (z / (1.0f + expf(-z)));
        v[j] = gv;
        ss += gv * gv;
    }
#pragma unroll
    for (int o = 16; o > 0; o >>= 1) ss += __shfl_xor_sync(0xffffffffu, ss, o);
    float sc = rsqrtf(ss * (1.0f / 256.0f) + 1e-5f);
    __nv_bfloat16* yh = (__nv_bfloat16*)g_y_hi;
    __nv_bfloat16* yl = (__nv_bfloat16*)g_y_lo;
#pragma unroll
    for (int j = 0; j < 8; j++) {
        int e = lane + j * 32;
        float r = v[j] * sc * __ldg(ng + e);
        __nv_bfloat16 h = __float2bfloat16(r);
        __nv_bfloat16 l = __float2bfloat16(r - __bfloat162float(h));
        size_t o = (size_t)warp * D_INNER + e;
        yh[o] = h; yl[o] = l;
    }
}

// ---------------------------------------------------------------------------
// K10: (m, c) -> NCHW
// ---------------------------------------------------------------------------
__global__ __launch_bounds__(256) void k_nchw(float* __restrict__ dst) {
    int by = blockIdx.x;
    int b = by >> 7, y = by & 127;
    int x0g = blockIdx.y * 64;
    __shared__ float tile[64][129];
    int tid = threadIdx.x;
    int cc = tid & 127;
    for (int xl = tid >> 7; xl < 64; xl += 2)
        tile[xl][cc] = g_buf1[((size_t)by * Ww + x0g + xl) * Cc + cc];
    __syncthreads();
    for (int i = tid; i < 64 * Cc; i += 256) {
        int xl = i & 63;
        int c = i >> 6;
        dst[(((size_t)b * Cc + c) * Hh + y) * Ww + x0g + xl] = tile[xl][c];
    }
}

// ---------------------------------------------------------------------------
extern "C" void kernel_launch(void* const* d_in, const int* in_sizes, int n_in,
                              void* d_out, int out_size) {
    const float* x        = (const float*)d_in[0];
    const float* dw_w     = (const float*)d_in[1];
    const float* gn_g     = (const float*)d_in[2];
    const float* gn_b     = (const float*)d_in[3];
    const float* pw_w     = (const float*)d_in[4];
    const float* pw_b     = (const float*)d_in[5];
    const float* in_projw = (const float*)d_in[6];
    const float* conv_w   = (const float*)d_in[7];
    const float* conv_b   = (const float*)d_in[8];
    const float* dt_bias  = (const float*)d_in[9];
    const float* A_log    = (const float*)d_in[10];
    const float* D_skip   = (const float*)d_in[11];
    const float* norm_g   = (const float*)d_in[12];
    const float* out_w    = (const float*)d_in[13];
    float* out = (float*)d_out;

    float *p_buf1, *p_zx, *p_ys, *p_off;
    uint4 *p_sh, *p_sl, *p_yh, *p_yl, *p_iph, *p_ipl, *p_owh, *p_owl;
    cudaGetSymbolAddress((void**)&p_buf1, g_buf1);
    cudaGetSymbolAddress((void**)&p_zx, g_zx);
    cudaGetSymbolAddress((void**)&p_ys, g_ys);
    cudaGetSymbolAddress((void**)&p_off, g_off);
    cudaGetSymbolAddress((void**)&p_sh, g_seq_hi);
    cudaGetSymbolAddress((void**)&p_sl, g_seq_lo);
    cudaGetSymbolAddress((void**)&p_yh, g_y_hi);
    cudaGetSymbolAddress((void**)&p_yl, g_y_lo);
    cudaGetSymbolAddress((void**)&p_iph, g_ipw_hi);
    cudaGetSymbolAddress((void**)&p_ipl, g_ipw_lo);
    cudaGetSymbolAddress((void**)&p_owh, g_ow_hi);
    cudaGetSymbolAddress((void**)&p_owl, g_ow_lo);

    cudaFuncSetAttribute(k_scan, cudaFuncAttributeMaxDynamicSharedMemorySize, SCAN_SMEM);
    cudaFuncSetAttribute(k_gemm_bf16, cudaFuncAttributeMaxDynamicSharedMemorySize, SMEM_GEMM);

    // front-end (5 launches) so in_proj GEMM is the 6th (ncu -s 5 -c 1 target)
    k_dwconv<<<OUT2D_ELEMS / 256, 256>>>(x, dw_w);
    k_gnstats<<<dim3(Bb, 8), 256>>>();
    k_offset<<<OFF_ELEMS / 256, 256>>>(gn_g, gn_b, pw_w, pw_b);
    k_sample<<<dim3(BS, 2), 256>>>(x);
    k_wsplit<<<(IPW_ELEMS + 255) / 256, 256>>>(in_projw, p_iph, p_ipl, IPW_ELEMS);

    // in_proj: (M=131072, N=648, K=128)   [6th launch]
    k_gemm_bf16<<<dim3((D_INPROJ + 63) / 64, MM / 128), 256, SMEM_GEMM>>>(
        p_sh, p_sl, p_iph, p_ipl, p_zx, D_INPROJ, 128, D_INPROJ);

    k_wsplit<<<(OW_ELEMS + 255) / 256, 256>>>(out_w, p_owh, p_owl, OW_ELEMS);

    k_conv1d<<<(MM * D_XBC) / 256, 256>>>(conv_w, conv_b);
    k_dt<<<(MM * NHEADS) / 256, 256>>>(dt_bias);
    k_scan<<<dim3(BS, NHEADS), 256, SCAN_SMEM>>>(A_log, D_skip);
    k_gatenorm<<<MM / 8, 256>>>(norm_g);

    // out proj: (M=131072, N=128, K=256)
    k_gemm_bf16<<<dim3(2, MM / 128), 256, SMEM_GEMM>>>(
        p_yh, p_yl, p_owh, p_owl, p_buf1, 128, 256, 128);

    k_nchw<<<dim3(BS, 2), 256>>>(out);

    if (out_size >= OUT2D_ELEMS + OFF_ELEMS)
        cudaMemcpyAsync(out + OUT2D_ELEMS, p_off, OFF_ELEMS * sizeof(float),
                        cudaMemcpyDeviceToDevice);
}

// round 9
// speedup vs baseline: 1.2956x; 1.1450x over previous
#include <cuda_runtime.h>
#include <cuda_bf16.h>
#include <math.h>
#include <stdint.h>

// ---------------------------------------------------------------------------
// SnakeScanBranch R8: traffic-fused pipeline.
//  - in_proj GEMM epilogue fuses causal conv1d+silu and dt softplus
//  - out GEMM epilogue writes NCHW directly
//  - scan grid reordered for 8x B/C L2 reuse
// GEMM core: bf16 mma.sync m16n8k16 + ldmatrix, 3-product hi/lo split.
// ---------------------------------------------------------------------------

#define Bb 8
#define Cc 128
#define Hh 128
#define Ww 128
#define HW 16384
#define D_INNER 256
#define D_STATE 64
#define NHEADS 8
#define D_XBC 384
#define D_INPROJ 648
#define BS 1024
#define LL 128
#define MM 131072
#define OUT2D_ELEMS 16777216
#define OFF_ELEMS 131072
#define IPW_ELEMS (D_INPROJ * 128)
#define OW_ELEMS  (128 * D_INNER)

// ---- scratch ---------------------------------------------------------------
__device__ float g_buf1[OUT2D_ELEMS];          // dwconv tmp
__device__ float g_z[(size_t)MM * 256];        // z part of in_proj (fp32)
__device__ float g_xbcc[(size_t)MM * D_XBC];   // conv1d+silu output
__device__ float g_dt[MM * NHEADS];
__device__ float g_ys[(size_t)MM * D_INNER];
__device__ float g_off[OFF_ELEMS];
__device__ float g_part[64 * 8 * 2];           // gn partial sums
__device__ uint4 g_seq_hi[(size_t)MM * 128 / 8];
__device__ uint4 g_seq_lo[(size_t)MM * 128 / 8];
__device__ uint4 g_y_hi[(size_t)MM * 256 / 8];
__device__ uint4 g_y_lo[(size_t)MM * 256 / 8];
__device__ uint4 g_ipw_hi[IPW_ELEMS / 8];
__device__ uint4 g_ipw_lo[IPW_ELEMS / 8];
__device__ uint4 g_ow_hi[OW_ELEMS / 8];
__device__ uint4 g_ow_lo[OW_ELEMS / 8];

// ---------------------------------------------------------------------------
__device__ __forceinline__ uint32_t smem_u32(const void* p) {
    uint32_t a;
    asm("{ .reg .u64 t; cvta.to.shared.u64 t, %1; cvt.u32.u64 %0, t; }"
        : "=r"(a) : "l"(p));
    return a;
}

#define LDSM4(r, addr)                                                        \
    asm volatile("ldmatrix.sync.aligned.m8n8.x4.shared.b16 {%0,%1,%2,%3}, [%4];" \
                 : "=r"((r)[0]), "=r"((r)[1]), "=r"((r)[2]), "=r"((r)[3])     \
                 : "r"(addr))

#define MMA_BF16(d, a, b0, b1)                                                \
    asm volatile(                                                             \
        "mma.sync.aligned.m16n8k16.row.col.f32.bf16.bf16.f32 "                \
        "{%0,%1,%2,%3}, {%4,%5,%6,%7}, {%8,%9}, {%0,%1,%2,%3};"               \
        : "+f"((d)[0]), "+f"((d)[1]), "+f"((d)[2]), "+f"((d)[3])              \
        : "r"((a)[0]), "r"((a)[1]), "r"((a)[2]), "r"((a)[3]), "r"(b0), "r"(b1))

// ---------------------------------------------------------------------------
// K1: depthwise 5x5 conv
// ---------------------------------------------------------------------------
__global__ __launch_bounds__(256) void k_dwconv(const float* __restrict__ x,
                                                const float* __restrict__ w) {
    int idx = blockIdx.x * 256 + threadIdx.x;
    int xx = idx & 127;
    int yy = (idx >> 7) & 127;
    int c  = (idx >> 14) & 127;
    const float* wp = w + c * 25;
    const float* plane = x + (idx - yy * Ww - xx);
    float acc = 0.0f;
#pragma unroll
    for (int ky = 0; ky < 5; ky++) {
        int sy = yy + ky - 2;
        if (sy < 0 || sy > 127) continue;
        const float* row = plane + sy * Ww;
#pragma unroll
        for (int kx = 0; kx < 5; kx++) {
            int sx = xx + kx - 2;
            if (sx < 0 || sx > 127) continue;
            acc += __ldg(row + sx) * __ldg(wp + ky * 5 + kx);
        }
    }
    g_buf1[idx] = acc;
}

// ---------------------------------------------------------------------------
// K2: groupnorm partial sums (512 blocks for parallelism; deterministic)
// ---------------------------------------------------------------------------
__global__ __launch_bounds__(256) void k_gnstats1() {
    int bg = blockIdx.x;                 // b*8+g (0..63)
    int part = blockIdx.y;               // 0..7
    const float* p = g_buf1 + (size_t)bg * 16 * HW + part * 32768;
    float s = 0.0f, ss = 0.0f;
    for (int i = threadIdx.x; i < 32768; i += 256) {
        float v = p[i];
        s += v; ss += v * v;
    }
    __shared__ float rs[256], rss[256];
    rs[threadIdx.x] = s; rss[threadIdx.x] = ss;
    __syncthreads();
    for (int o = 128; o > 0; o >>= 1) {
        if (threadIdx.x < o) { rs[threadIdx.x] += rs[threadIdx.x + o]; rss[threadIdx.x] += rss[threadIdx.x + o]; }
        __syncthreads();
    }
    if (threadIdx.x == 0) {
        g_part[(bg * 8 + part) * 2]     = rs[0];
        g_part[(bg * 8 + part) * 2 + 1] = rss[0];
    }
}

// ---------------------------------------------------------------------------
// K3: finalize stats + gelu(gn) -> pointwise -> tanh*8
// ---------------------------------------------------------------------------
__global__ __launch_bounds__(256) void k_offset(const float* __restrict__ gn_g,
                                                const float* __restrict__ gn_b,
                                                const float* __restrict__ pw_w,
                                                const float* __restrict__ pw_b) {
    __shared__ float s_mean[8], s_rstd[8];
    int idx = blockIdx.x * 256 + threadIdx.x;
    int b = idx >> 14;
    int pix = idx & 16383;
    if (threadIdx.x < 8) {
        int gg = threadIdx.x;
        float s = 0.0f, ss = 0.0f;
        for (int p = 0; p < 8; p++) {
            s  += g_part[((b * 8 + gg) * 8 + p) * 2];
            ss += g_part[((b * 8 + gg) * 8 + p) * 2 + 1];
        }
        const float inv = 1.0f / (16.0f * HW);
        float mean = s * inv;
        float var  = ss * inv - mean * mean;
        s_mean[gg] = mean;
        s_rstd[gg] = rsqrtf(var + 1e-5f);
    }
    __syncthreads();
    float acc = 0.0f;
    for (int c = 0; c < Cc; c++) {
        float v = g_buf1[((size_t)b * Cc + c) * HW + pix];
        int grp = c >> 4;
        float u = (v - s_mean[grp]) * s_rstd[grp] * __ldg(gn_g + c) + __ldg(gn_b + c);
        float ge = 0.5f * u * (1.0f + erff(u * 0.70710678118654752440f));
        acc += __ldg(pw_w + c) * ge;
    }
    acc += __ldg(pw_b);
    g_off[idx] = tanhf(acc) * 8.0f;
}

// ---------------------------------------------------------------------------
// K4: grid sample (bilinear, border) -> seq bf16 hi/lo
// ---------------------------------------------------------------------------
__global__ __launch_bounds__(256) void k_sample(const float* __restrict__ x) {
    int by = blockIdx.x;
    int b = by >> 7, y = by & 127;
    int x0g = blockIdx.y * 64;
    __shared__ float tile[64][129];
    __shared__ int s_y0[64], s_y1[64], s_x0[64], s_x1[64];
    __shared__ float s_wx[64], s_wy[64];
    int tid = threadIdx.x;
    if (tid < 64) {
        int xg = x0g + tid;
        float off_n = g_off[by * Ww + xg] * (2.0f / 127.0f);
        float byv = -1.0f + y  * (2.0f / 127.0f);
        float bxv = -1.0f + xg * (2.0f / 127.0f);
        float gyv = fminf(fmaxf(byv + off_n, -1.0f), 1.0f);
        float gx = fminf(fmaxf((bxv + 1.0f) * 0.5f * 127.0f, 0.0f), 127.0f);
        float gy = fminf(fmaxf((gyv + 1.0f) * 0.5f * 127.0f, 0.0f), 127.0f);
        float fx0 = floorf(gx), fy0 = floorf(gy);
        s_wx[tid] = gx - fx0;
        s_wy[tid] = gy - fy0;
        int x0i = (int)fx0, y0i = (int)fy0;
        s_x0[tid] = x0i; s_y0[tid] = y0i;
        s_x1[tid] = min(x0i + 1, 127);
        s_y1[tid] = min(y0i + 1, 127);
    }
    __syncthreads();
    for (int i = tid; i < 64 * Cc; i += 256) {
        int xl = i & 63;
        int c = i >> 6;
        const float* pl = x + ((size_t)b * Cc + c) * HW;
        float wx = s_wx[xl], wy = s_wy[xl];
        int r0 = s_y0[xl] * Ww, r1 = s_y1[xl] * Ww;
        float v00 = __ldg(pl + r0 + s_x0[xl]);
        float v01 = __ldg(pl + r0 + s_x1[xl]);
        float v10 = __ldg(pl + r1 + s_x0[xl]);
        float v11 = __ldg(pl + r1 + s_x1[xl]);
        float top = v00 * (1.0f - wx) + v01 * wx;
        float bot = v10 * (1.0f - wx) + v11 * wx;
        tile[xl][c] = top * (1.0f - wy) + bot * wy;
    }
    __syncthreads();
    __nv_bfloat16* sh = (__nv_bfloat16*)g_seq_hi;
    __nv_bfloat16* sl = (__nv_bfloat16*)g_seq_lo;
    for (int i = tid; i < 64 * Cc; i += 256) {
        int xl = i >> 7;
        int c = i & 127;
        float v = tile[xl][c];
        __nv_bfloat16 h = __float2bfloat16(v);
        __nv_bfloat16 l = __float2bfloat16(v - __bfloat162float(h));
        size_t o = ((size_t)by * Ww + x0g + xl) * 128 + c;
        sh[o] = h; sl[o] = l;
    }
}

// ---------------------------------------------------------------------------
// Weight split fp32 -> bf16 hi + lo
// ---------------------------------------------------------------------------
__global__ __launch_bounds__(256) void k_wsplit(const float* __restrict__ w,
                                                uint4* __restrict__ hi4,
                                                uint4* __restrict__ lo4, int n) {
    int i = blockIdx.x * 256 + threadIdx.x;
    if (i >= n) return;
    float v = w[i];
    __nv_bfloat16 h = __float2bfloat16(v);
    __nv_bfloat16 l = __float2bfloat16(v - __bfloat162float(h));
    ((__nv_bfloat16*)hi4)[i] = h;
    ((__nv_bfloat16*)lo4)[i] = l;
}

// ---------------------------------------------------------------------------
// bf16x3 GEMM with fused epilogues.
// mode 1 (in_proj): n0<256 -> g_z; 256<=n0<640 -> conv1d+silu -> g_xbcc;
//                   n0=640 -> softplus dt -> g_dt.
// mode 2 (out proj): write NCHW directly to outp.
// BM=128 (= one sequence) BN=64, K chunks of 128. 8 warps, ldmatrix + mma.
// ---------------------------------------------------------------------------
#define APAD 136
#define SM_AHI 0
#define SM_ALO 34816
#define SM_BHI 69632
#define SM_BLO 87040
#define SMEM_GEMM 104448

__global__ __launch_bounds__(256) void k_gemm(const uint4* __restrict__ Ahi,
                                              const uint4* __restrict__ Alo,
                                              const uint4* __restrict__ Bhi,
                                              const uint4* __restrict__ Blo,
                                              float* __restrict__ outp,
                                              const float* __restrict__ cw,
                                              const float* __restrict__ cb,
                                              const float* __restrict__ dtb,
                                              int N, int K, int mode) {
    extern __shared__ char sm[];
    uint32_t smb = smem_u32(sm);
    int tid = threadIdx.x;
    int lane = tid & 31;
    int wid = tid >> 5;
    int wm = (wid >> 1) * 32;
    int wn = (wid & 1) * 32;
    int m0 = blockIdx.y * 128;
    int n0 = blockIdx.x * 64;
    int K8 = K >> 3;

    float acc[2][4][4];
#pragma unroll
    for (int mi = 0; mi < 2; mi++)
#pragma unroll
        for (int ni = 0; ni < 4; ni++)
#pragma unroll
            for (int j = 0; j < 4; j++) acc[mi][ni][j] = 0.0f;

    int a_r  = lane & 15;
    int a_c8 = (lane >> 4) << 3;
    uint32_t a_base = ((uint32_t)(wm + a_r) * APAD + a_c8) * 2;
    int b_r  = (lane & 7) + ((lane >> 4) << 3);
    int b_c8 = ((lane >> 3) & 1) << 3;
    uint32_t b_base = ((uint32_t)(wn + b_r) * APAD + b_c8) * 2;

    int nchunks = K >> 7;
    for (int ch = 0; ch < nchunks; ch++) {
        if (ch) __syncthreads();
        int kc8 = ch << 4;
#pragma unroll
        for (int it = 0; it < 8; it++) {
            int g = it * 256 + tid;
            int row = g >> 4, kg = g & 15;
            size_t go = (size_t)(m0 + row) * K8 + kc8 + kg;
            uint32_t so = ((uint32_t)row * APAD + kg * 8) * 2;
            *(uint4*)(sm + SM_AHI + so) = Ahi[go];
            *(uint4*)(sm + SM_ALO + so) = Alo[go];
        }
#pragma unroll
        for (int it = 0; it < 4; it++) {
            int g = it * 256 + tid;
            int row = g >> 4, kg = g & 15;
            uint4 h = make_uint4(0, 0, 0, 0), l = make_uint4(0, 0, 0, 0);
            if (n0 + row < N) {
                size_t go = (size_t)(n0 + row) * K8 + kc8 + kg;
                h = Bhi[go]; l = Blo[go];
            }
            uint32_t so = ((uint32_t)row * APAD + kg * 8) * 2;
            *(uint4*)(sm + SM_BHI + so) = h;
            *(uint4*)(sm + SM_BLO + so) = l;
        }
        __syncthreads();
#pragma unroll
        for (int k16 = 0; k16 < 8; k16++) {
            uint32_t kb2 = (uint32_t)(k16 * 16) * 2;
            uint32_t Ah[2][4], Al[2][4], Bh[2][4], Bl[2][4];
#pragma unroll
            for (int mi = 0; mi < 2; mi++) {
                uint32_t ad = smb + a_base + (uint32_t)mi * (16 * APAD * 2) + kb2;
                LDSM4(Ah[mi], ad + SM_AHI);
                LDSM4(Al[mi], ad + SM_ALO);
            }
#pragma unroll
            for (int nj = 0; nj < 2; nj++) {
                uint32_t bd = smb + b_base + (uint32_t)nj * (16 * APAD * 2) + kb2;
                LDSM4(Bh[nj], bd + SM_BHI);
                LDSM4(Bl[nj], bd + SM_BLO);
            }
#pragma unroll
            for (int mi = 0; mi < 2; mi++)
#pragma unroll
                for (int nj = 0; nj < 2; nj++) {
                    MMA_BF16(acc[mi][2 * nj + 0], Ah[mi], Bh[nj][0], Bh[nj][1]);
                    MMA_BF16(acc[mi][2 * nj + 0], Ah[mi], Bl[nj][0], Bl[nj][1]);
                    MMA_BF16(acc[mi][2 * nj + 0], Al[mi], Bh[nj][0], Bh[nj][1]);
                    MMA_BF16(acc[mi][2 * nj + 1], Ah[mi], Bh[nj][2], Bh[nj][3]);
                    MMA_BF16(acc[mi][2 * nj + 1], Ah[mi], Bl[nj][2], Bl[nj][3]);
                    MMA_BF16(acc[mi][2 * nj + 1], Al[mi], Bh[nj][2], Bh[nj][3]);
                }
        }
    }

    // ---- fused epilogues (reuse smem; all compute done) ----
    __syncthreads();
    float* st = (float*)sm;
    int g = lane >> 2, t = lane & 3;

    if (mode == 2) {
        // stage [c][x] (pad 132), write NCHW
#pragma unroll
        for (int mi = 0; mi < 2; mi++)
#pragma unroll
            for (int ni = 0; ni < 4; ni++) {
                int r = wm + mi * 16 + g;
                int c = wn + ni * 8 + t * 2;
                st[c * 132 + r]           = acc[mi][ni][0];
                st[(c + 1) * 132 + r]     = acc[mi][ni][1];
                st[c * 132 + r + 8]       = acc[mi][ni][2];
                st[(c + 1) * 132 + r + 8] = acc[mi][ni][3];
            }
        __syncthreads();
        int seq = m0 >> 7;
        int b = seq >> 7, y = seq & 127;
#pragma unroll
        for (int j = 0; j < 32; j++) {
            int idx = j * 256 + tid;
            int c = idx >> 7, xx = idx & 127;
            outp[(((size_t)b * 128 + n0 + c) * 128 + y) * 128 + xx] = st[c * 132 + xx];
        }
        return;
    }

    // mode 1: stage [l][e] (pad 72, float2 conflict-free)
#pragma unroll
    for (int mi = 0; mi < 2; mi++)
#pragma unroll
        for (int ni = 0; ni < 4; ni++) {
            int r = wm + mi * 16 + g;
            int c = wn + ni * 8 + t * 2;
            *(float2*)&st[r * 72 + c] = make_float2(acc[mi][ni][0], acc[mi][ni][1]);
            *(float2*)&st[(r + 8) * 72 + c] = make_float2(acc[mi][ni][2], acc[mi][ni][3]);
        }
    __syncthreads();

    if (n0 < 256) {
        // z region -> g_z fp32
#pragma unroll
        for (int j = 0; j < 32; j++) {
            int idx = j * 256 + tid;
            int r = idx >> 6, c = idx & 63;
            g_z[(size_t)(m0 + r) * 256 + n0 + c] = st[r * 72 + c];
        }
    } else if (n0 < 640) {
        // xBC region: causal conv1d (4 taps) + bias + silu -> g_xbcc
        int e = tid & 63;
        int eg = n0 - 256 + e;
        float4 w4 = *(const float4*)(cw + eg * 4);
        float bia = __ldg(cb + eg);
        int lb = (tid >> 6) * 32;
        float x0 = (lb >= 3) ? st[(lb - 3) * 72 + e] : 0.0f;
        float x1 = (lb >= 2) ? st[(lb - 2) * 72 + e] : 0.0f;
        float x2 = (lb >= 1) ? st[(lb - 1) * 72 + e] : 0.0f;
#pragma unroll 8
        for (int l = lb; l < lb + 32; l++) {
            float x3 = st[l * 72 + e];
            float a = bia + w4.x * x0 + w4.y * x1 + w4.z * x2 + w4.w * x3;
            x0 = x1; x1 = x2; x2 = x3;
            g_xbcc[(size_t)(m0 + l) * 384 + eg] = a / (1.0f + expf(-a));
        }
    } else {
        // dt region (8 cols): softplus(acc + dt_bias)
#pragma unroll
        for (int j = 0; j < 4; j++) {
            int idx = j * 256 + tid;
            int r = idx >> 3, hc = idx & 7;
            float v = st[r * 72 + hc] + __ldg(dtb + hc);
            g_dt[(size_t)(m0 + r) * 8 + hc] =
                fmaxf(v, 0.0f) + log1pf(expf(-fabsf(v)));
        }
    }
}

// ---------------------------------------------------------------------------
// K7: selective scan. Block per (head, seq) — heads of one seq adjacent for
// L2 reuse of B/C.
// ---------------------------------------------------------------------------
#define SCAN_SMEM ((8192 + 8192 + 4096 + 128 + 128) * 4)
__global__ __launch_bounds__(256) void k_scan(const float* __restrict__ A_log,
                                              const float* __restrict__ Dskip) {
    extern __shared__ float smf[];
    float* sB  = smf;
    float* sC  = sB + 8192;
    float* sx  = sC + 8192;
    float* sdt = sx + 4096;
    float* sdA = sdt + 128;
    int hh = blockIdx.x, bs = blockIdx.y;
    int tid = threadIdx.x;
    float Ah = -expf(__ldg(A_log + hh));
    float Dh = __ldg(Dskip + hh);

    const float* base = g_xbcc + (size_t)bs * LL * D_XBC;
    for (int i = tid; i < 128 * 64; i += 256) {
        int l = i >> 6, s = i & 63;
        sB[i] = base[l * D_XBC + D_INNER + s];
        sC[i] = base[l * D_XBC + D_INNER + D_STATE + s];
    }
    for (int i = tid; i < 128 * 32; i += 256) {
        int l = i >> 5, d = i & 31;
        sx[i] = base[l * D_XBC + hh * 32 + d];
    }
    if (tid < 128) {
        float v = g_dt[((size_t)bs * LL + tid) * NHEADS + hh];
        sdt[tid] = v;
        sdA[tid] = expf(v * Ah);
    }
    __syncthreads();

    int d = tid >> 3;
    int s8 = tid & 7;
    int sb = s8 * 8;
    float h[8] = {0, 0, 0, 0, 0, 0, 0, 0};
    float* ysout = g_ys + ((size_t)bs * LL) * D_INNER + hh * 32 + d;

    for (int l = 0; l < LL; l++) {
        float dtv = sdt[l];
        float dA = sdA[l];
        float xv = sx[l * 32 + d];
        float cf = dtv * xv;
        float4 b0 = *(const float4*)&sB[l * 64 + sb];
        float4 b1 = *(const float4*)&sB[l * 64 + sb + 4];
        float4 c0 = *(const float4*)&sC[l * 64 + sb];
        float4 c1 = *(const float4*)&sC[l * 64 + sb + 4];
        float y = 0.0f;
        h[0] = h[0] * dA + cf * b0.x; y += h[0] * c0.x;
        h[1] = h[1] * dA + cf * b0.y; y += h[1] * c0.y;
        h[2] = h[2] * dA + cf * b0.z; y += h[2] * c0.z;
        h[3] = h[3] * dA + cf * b0.w; y += h[3] * c0.w;
        h[4] = h[4] * dA + cf * b1.x; y += h[4] * c1.x;
        h[5] = h[5] * dA + cf * b1.y; y += h[5] * c1.y;
        h[6] = h[6] * dA + cf * b1.z; y += h[6] * c1.z;
        h[7] = h[7] * dA + cf * b1.w; y += h[7] * c1.w;
        y += __shfl_down_sync(0xffffffffu, y, 4, 8);
        y += __shfl_down_sync(0xffffffffu, y, 2, 8);
        y += __shfl_down_sync(0xffffffffu, y, 1, 8);
        if (s8 == 0) ysout[(size_t)l * D_INNER] = y + Dh * xv;
    }
}

// ---------------------------------------------------------------------------
// K8: gated RMSNorm -> bf16 hi/lo for out GEMM
// ---------------------------------------------------------------------------
__global__ __launch_bounds__(256) void k_gatenorm(const float* __restrict__ ng) {
    int warp = (blockIdx.x * 256 + threadIdx.x) >> 5;
    int lane = threadIdx.x & 31;
    const float* yrow = g_ys + (size_t)warp * D_INNER;
    const float* zrow = g_z + (size_t)warp * 256;
    float v[8];
    float ss = 0.0f;
#pragma unroll
    for (int j = 0; j < 8; j++) {
        int e = lane + j * 32;
        float z = zrow[e];
        float gv = yrow[e] * (z / (1.0f + expf(-z)));
        v[j] = gv;
        ss += gv * gv;
    }
#pragma unroll
    for (int o = 16; o > 0; o >>= 1) ss += __shfl_xor_sync(0xffffffffu, ss, o);
    float sc = rsqrtf(ss * (1.0f / 256.0f) + 1e-5f);
    __nv_bfloat16* yh = (__nv_bfloat16*)g_y_hi;
    __nv_bfloat16* yl = (__nv_bfloat16*)g_y_lo;
#pragma unroll
    for (int j = 0; j < 8; j++) {
        int e = lane + j * 32;
        float r = v[j] * sc * __ldg(ng + e);
        __nv_bfloat16 h = __float2bfloat16(r);
        __nv_bfloat16 l = __float2bfloat16(r - __bfloat162float(h));
        size_t o = (size_t)warp * D_INNER + e;
        yh[o] = h; yl[o] = l;
    }
}

// ---------------------------------------------------------------------------
extern "C" void kernel_launch(void* const* d_in, const int* in_sizes, int n_in,
                              void* d_out, int out_size) {
    const float* x        = (const float*)d_in[0];
    const float* dw_w     = (const float*)d_in[1];
    const float* gn_g     = (const float*)d_in[2];
    const float* gn_b     = (const float*)d_in[3];
    const float* pw_w     = (const float*)d_in[4];
    const float* pw_b     = (const float*)d_in[5];
    const float* in_projw = (const float*)d_in[6];
    const float* conv_w   = (const float*)d_in[7];
    const float* conv_b   = (const float*)d_in[8];
    const float* dt_bias  = (const float*)d_in[9];
    const float* A_log    = (const float*)d_in[10];
    const float* D_skip   = (const float*)d_in[11];
    const float* norm_g   = (const float*)d_in[12];
    const float* out_w    = (const float*)d_in[13];
    float* out = (float*)d_out;

    float *p_off;
    uint4 *p_sh, *p_sl, *p_yh, *p_yl, *p_iph, *p_ipl, *p_owh, *p_owl;
    cudaGetSymbolAddress((void**)&p_off, g_off);
    cudaGetSymbolAddress((void**)&p_sh, g_seq_hi);
    cudaGetSymbolAddress((void**)&p_sl, g_seq_lo);
    cudaGetSymbolAddress((void**)&p_yh, g_y_hi);
    cudaGetSymbolAddress((void**)&p_yl, g_y_lo);
    cudaGetSymbolAddress((void**)&p_iph, g_ipw_hi);
    cudaGetSymbolAddress((void**)&p_ipl, g_ipw_lo);
    cudaGetSymbolAddress((void**)&p_owh, g_ow_hi);
    cudaGetSymbolAddress((void**)&p_owl, g_ow_lo);

    cudaFuncSetAttribute(k_scan, cudaFuncAttributeMaxDynamicSharedMemorySize, SCAN_SMEM);
    cudaFuncSetAttribute(k_gemm, cudaFuncAttributeMaxDynamicSharedMemorySize, SMEM_GEMM);

    // 1..5
    k_dwconv<<<OUT2D_ELEMS / 256, 256>>>(x, dw_w);
    k_gnstats1<<<dim3(64, 8), 256>>>();
    k_offset<<<OFF_ELEMS / 256, 256>>>(gn_g, gn_b, pw_w, pw_b);
    k_sample<<<dim3(BS, 2), 256>>>(x);
    k_wsplit<<<(IPW_ELEMS + 255) / 256, 256>>>(in_projw, p_iph, p_ipl, IPW_ELEMS);

    // 6: in_proj GEMM + fused conv1d/silu/dt epilogue
    k_gemm<<<dim3((D_INPROJ + 63) / 64, MM / 128), 256, SMEM_GEMM>>>(
        p_sh, p_sl, p_iph, p_ipl, nullptr, conv_w, conv_b, dt_bias,
        D_INPROJ, 128, 1);

    k_wsplit<<<(OW_ELEMS + 255) / 256, 256>>>(out_w, p_owh, p_owl, OW_ELEMS);

    // scan: heads of one sequence adjacent in block order
    k_scan<<<dim3(NHEADS, BS), 256, SCAN_SMEM>>>(A_log, D_skip);

    k_gatenorm<<<MM / 8, 256>>>(norm_g);

    // out proj GEMM + fused NCHW epilogue (writes d_out directly)
    k_gemm<<<dim3(2, MM / 128), 256, SMEM_GEMM>>>(
        p_yh, p_yl, p_owh, p_owl, out, nullptr, nullptr, nullptr,
        128, 256, 2);

    if (out_size >= OUT2D_ELEMS + OFF_ELEMS)
        cudaMemcpyAsync(out + OUT2D_ELEMS, p_off, OFF_ELEMS * sizeof(float),
                        cudaMemcpyDeviceToDevice);
}

// round 10
// speedup vs baseline: 2.2073x; 1.7036x over previous
#include <cuda_runtime.h>
#include <cuda_bf16.h>
#include <cuda_fp16.h>
#include <math.h>
#include <stdint.h>

// ---------------------------------------------------------------------------
// SnakeScanBranch R9:
//  - k_scanorm: selective scan + gated RMSNorm fused (no ys round trip)
//  - GEMMs: fp16 mma, A single-precision-fp16, B weights split hi/lo (2-product)
//  - in_proj epilogue: conv1d+silu+dt (as R8); out epilogue: direct NCHW
// ---------------------------------------------------------------------------

#define Bb 8
#define Cc 128
#define Hh 128
#define Ww 128
#define HW 16384
#define D_INNER 256
#define D_STATE 64
#define NHEADS 8
#define D_XBC 384
#define D_INPROJ 648
#define BS 1024
#define LL 128
#define MM 131072
#define OUT2D_ELEMS 16777216
#define OFF_ELEMS 131072
#define IPW_ELEMS (D_INPROJ * 128)
#define OW_ELEMS  (128 * D_INNER)

// ---- scratch ---------------------------------------------------------------
__device__ float g_buf1[OUT2D_ELEMS];          // dwconv tmp
__device__ float g_z[(size_t)MM * 256];        // z (fp32)
__device__ float g_xbcc[(size_t)MM * D_XBC];   // conv1d+silu output
__device__ float g_dt[MM * NHEADS];
__device__ float g_off[OFF_ELEMS];
__device__ float g_part[64 * 8 * 2];
__device__ uint4 g_seq_h[(size_t)MM * 128 / 8];   // fp16 seq
__device__ uint4 g_y_h[(size_t)MM * 256 / 8];     // fp16 normalized y
__device__ uint4 g_ipw_hi[IPW_ELEMS / 8];         // fp16 weight hi
__device__ uint4 g_ipw_lo[IPW_ELEMS / 8];         // fp16 weight lo
__device__ uint4 g_ow_hi[OW_ELEMS / 8];
__device__ uint4 g_ow_lo[OW_ELEMS / 8];

// ---------------------------------------------------------------------------
__device__ __forceinline__ uint32_t smem_u32(const void* p) {
    uint32_t a;
    asm("{ .reg .u64 t; cvta.to.shared.u64 t, %1; cvt.u32.u64 %0, t; }"
        : "=r"(a) : "l"(p));
    return a;
}

#define LDSM4(r, addr)                                                        \
    asm volatile("ldmatrix.sync.aligned.m8n8.x4.shared.b16 {%0,%1,%2,%3}, [%4];" \
                 : "=r"((r)[0]), "=r"((r)[1]), "=r"((r)[2]), "=r"((r)[3])     \
                 : "r"(addr))

#define MMA_F16(d, a, b0, b1)                                                 \
    asm volatile(                                                             \
        "mma.sync.aligned.m16n8k16.row.col.f32.f16.f16.f32 "                  \
        "{%0,%1,%2,%3}, {%4,%5,%6,%7}, {%8,%9}, {%0,%1,%2,%3};"               \
        : "+f"((d)[0]), "+f"((d)[1]), "+f"((d)[2]), "+f"((d)[3])              \
        : "r"((a)[0]), "r"((a)[1]), "r"((a)[2]), "r"((a)[3]), "r"(b0), "r"(b1))

// ---------------------------------------------------------------------------
// K1: depthwise 5x5 conv
// ---------------------------------------------------------------------------
__global__ __launch_bounds__(256) void k_dwconv(const float* __restrict__ x,
                                                const float* __restrict__ w) {
    int idx = blockIdx.x * 256 + threadIdx.x;
    int xx = idx & 127;
    int yy = (idx >> 7) & 127;
    int c  = (idx >> 14) & 127;
    const float* wp = w + c * 25;
    const float* plane = x + (idx - yy * Ww - xx);
    float acc = 0.0f;
#pragma unroll
    for (int ky = 0; ky < 5; ky++) {
        int sy = yy + ky - 2;
        if (sy < 0 || sy > 127) continue;
        const float* row = plane + sy * Ww;
#pragma unroll
        for (int kx = 0; kx < 5; kx++) {
            int sx = xx + kx - 2;
            if (sx < 0 || sx > 127) continue;
            acc += __ldg(row + sx) * __ldg(wp + ky * 5 + kx);
        }
    }
    g_buf1[idx] = acc;
}

// ---------------------------------------------------------------------------
// K2: groupnorm partial sums
// ---------------------------------------------------------------------------
__global__ __launch_bounds__(256) void k_gnstats1() {
    int bg = blockIdx.x;
    int part = blockIdx.y;
    const float* p = g_buf1 + (size_t)bg * 16 * HW + part * 32768;
    float s = 0.0f, ss = 0.0f;
    for (int i = threadIdx.x; i < 32768; i += 256) {
        float v = p[i];
        s += v; ss += v * v;
    }
    __shared__ float rs[256], rss[256];
    rs[threadIdx.x] = s; rss[threadIdx.x] = ss;
    __syncthreads();
    for (int o = 128; o > 0; o >>= 1) {
        if (threadIdx.x < o) { rs[threadIdx.x] += rs[threadIdx.x + o]; rss[threadIdx.x] += rss[threadIdx.x + o]; }
        __syncthreads();
    }
    if (threadIdx.x == 0) {
        g_part[(bg * 8 + part) * 2]     = rs[0];
        g_part[(bg * 8 + part) * 2 + 1] = rss[0];
    }
}

// ---------------------------------------------------------------------------
// K3: finalize stats + gelu(gn) -> pointwise -> tanh*8
// ---------------------------------------------------------------------------
__global__ __launch_bounds__(256) void k_offset(const float* __restrict__ gn_g,
                                                const float* __restrict__ gn_b,
                                                const float* __restrict__ pw_w,
                                                const float* __restrict__ pw_b) {
    __shared__ float s_mean[8], s_rstd[8];
    int idx = blockIdx.x * 256 + threadIdx.x;
    int b = idx >> 14;
    int pix = idx & 16383;
    if (threadIdx.x < 8) {
        int gg = threadIdx.x;
        float s = 0.0f, ss = 0.0f;
        for (int p = 0; p < 8; p++) {
            s  += g_part[((b * 8 + gg) * 8 + p) * 2];
            ss += g_part[((b * 8 + gg) * 8 + p) * 2 + 1];
        }
        const float inv = 1.0f / (16.0f * HW);
        float mean = s * inv;
        float var  = ss * inv - mean * mean;
        s_mean[gg] = mean;
        s_rstd[gg] = rsqrtf(var + 1e-5f);
    }
    __syncthreads();
    float acc = 0.0f;
    for (int c = 0; c < Cc; c++) {
        float v = g_buf1[((size_t)b * Cc + c) * HW + pix];
        int grp = c >> 4;
        float u = (v - s_mean[grp]) * s_rstd[grp] * __ldg(gn_g + c) + __ldg(gn_b + c);
        float ge = 0.5f * u * (1.0f + erff(u * 0.70710678118654752440f));
        acc += __ldg(pw_w + c) * ge;
    }
    acc += __ldg(pw_b);
    g_off[idx] = tanhf(acc) * 8.0f;
}

// ---------------------------------------------------------------------------
// K4: grid sample (bilinear, border) -> seq fp16
// ---------------------------------------------------------------------------
__global__ __launch_bounds__(256) void k_sample(const float* __restrict__ x) {
    int by = blockIdx.x;
    int b = by >> 7, y = by & 127;
    int x0g = blockIdx.y * 64;
    __shared__ float tile[64][129];
    __shared__ int s_y0[64], s_y1[64], s_x0[64], s_x1[64];
    __shared__ float s_wx[64], s_wy[64];
    int tid = threadIdx.x;
    if (tid < 64) {
        int xg = x0g + tid;
        float off_n = g_off[by * Ww + xg] * (2.0f / 127.0f);
        float byv = -1.0f + y  * (2.0f / 127.0f);
        float bxv = -1.0f + xg * (2.0f / 127.0f);
        float gyv = fminf(fmaxf(byv + off_n, -1.0f), 1.0f);
        float gx = fminf(fmaxf((bxv + 1.0f) * 0.5f * 127.0f, 0.0f), 127.0f);
        float gy = fminf(fmaxf((gyv + 1.0f) * 0.5f * 127.0f, 0.0f), 127.0f);
        float fx0 = floorf(gx), fy0 = floorf(gy);
        s_wx[tid] = gx - fx0;
        s_wy[tid] = gy - fy0;
        int x0i = (int)fx0, y0i = (int)fy0;
        s_x0[tid] = x0i; s_y0[tid] = y0i;
        s_x1[tid] = min(x0i + 1, 127);
        s_y1[tid] = min(y0i + 1, 127);
    }
    __syncthreads();
    for (int i = tid; i < 64 * Cc; i += 256) {
        int xl = i & 63;
        int c = i >> 6;
        const float* pl = x + ((size_t)b * Cc + c) * HW;
        float wx = s_wx[xl], wy = s_wy[xl];
        int r0 = s_y0[xl] * Ww, r1 = s_y1[xl] * Ww;
        float v00 = __ldg(pl + r0 + s_x0[xl]);
        float v01 = __ldg(pl + r0 + s_x1[xl]);
        float v10 = __ldg(pl + r1 + s_x0[xl]);
        float v11 = __ldg(pl + r1 + s_x1[xl]);
        float top = v00 * (1.0f - wx) + v01 * wx;
        float bot = v10 * (1.0f - wx) + v11 * wx;
        tile[xl][c] = top * (1.0f - wy) + bot * wy;
    }
    __syncthreads();
    __half* sh = (__half*)g_seq_h;
    for (int i = tid; i < 64 * Cc; i += 256) {
        int xl = i >> 7;
        int c = i & 127;
        size_t o = ((size_t)by * Ww + x0g + xl) * 128 + c;
        sh[o] = __float2half(tile[xl][c]);
    }
}

// ---------------------------------------------------------------------------
// Weight split fp32 -> fp16 hi + fp16 lo
// ---------------------------------------------------------------------------
__global__ __launch_bounds__(256) void k_wsplit(const float* __restrict__ w,
                                                uint4* __restrict__ hi4,
                                                uint4* __restrict__ lo4, int n) {
    int i = blockIdx.x * 256 + threadIdx.x;
    if (i >= n) return;
    float v = w[i];
    __half h = __float2half(v);
    __half l = __float2half(v - __half2float(h));
    ((__half*)hi4)[i] = h;
    ((__half*)lo4)[i] = l;
}

// ---------------------------------------------------------------------------
// fp16 GEMM (A single, B 2-product hi/lo): C = A * B^T
// BM=128 BN=64, K chunks of 128. mode 1: in_proj fused epilogue
// (z / conv1d+silu / dt). mode 2: out proj, NCHW epilogue.
// ---------------------------------------------------------------------------
#define APAD 136
#define SM_A  0
#define SM_BH 34816                   // 128*136*2
#define SM_BL 52224                   // + 64*136*2
#define SMEM_GEMM 69632               // + 64*136*2

__global__ __launch_bounds__(256) void k_gemm(const uint4* __restrict__ A,
                                              const uint4* __restrict__ Bhi,
                                              const uint4* __restrict__ Blo,
                                              float* __restrict__ outp,
                                              const float* __restrict__ cw,
                                              const float* __restrict__ cb,
                                              const float* __restrict__ dtb,
                                              int N, int K, int mode) {
    extern __shared__ char sm[];
    uint32_t smb = smem_u32(sm);
    int tid = threadIdx.x;
    int lane = tid & 31;
    int wid = tid >> 5;
    int wm = (wid >> 1) * 32;
    int wn = (wid & 1) * 32;
    int m0 = blockIdx.y * 128;
    int n0 = blockIdx.x * 64;
    int K8 = K >> 3;

    float acc[2][4][4];
#pragma unroll
    for (int mi = 0; mi < 2; mi++)
#pragma unroll
        for (int ni = 0; ni < 4; ni++)
#pragma unroll
            for (int j = 0; j < 4; j++) acc[mi][ni][j] = 0.0f;

    int a_r  = lane & 15;
    int a_c8 = (lane >> 4) << 3;
    uint32_t a_base = ((uint32_t)(wm + a_r) * APAD + a_c8) * 2;
    int b_r  = (lane & 7) + ((lane >> 4) << 3);
    int b_c8 = ((lane >> 3) & 1) << 3;
    uint32_t b_base = ((uint32_t)(wn + b_r) * APAD + b_c8) * 2;

    int nchunks = K >> 7;
    for (int ch = 0; ch < nchunks; ch++) {
        if (ch) __syncthreads();
        int kc8 = ch << 4;
#pragma unroll
        for (int it = 0; it < 8; it++) {
            int g = it * 256 + tid;
            int row = g >> 4, kg = g & 15;
            size_t go = (size_t)(m0 + row) * K8 + kc8 + kg;
            uint32_t so = ((uint32_t)row * APAD + kg * 8) * 2;
            *(uint4*)(sm + SM_A + so) = A[go];
        }
#pragma unroll
        for (int it = 0; it < 4; it++) {
            int g = it * 256 + tid;
            int row = g >> 4, kg = g & 15;
            uint4 h = make_uint4(0, 0, 0, 0), l = make_uint4(0, 0, 0, 0);
            if (n0 + row < N) {
                size_t go = (size_t)(n0 + row) * K8 + kc8 + kg;
                h = Bhi[go]; l = Blo[go];
            }
            uint32_t so = ((uint32_t)row * APAD + kg * 8) * 2;
            *(uint4*)(sm + SM_BH + so) = h;
            *(uint4*)(sm + SM_BL + so) = l;
        }
        __syncthreads();
#pragma unroll
        for (int k16 = 0; k16 < 8; k16++) {
            uint32_t kb2 = (uint32_t)(k16 * 16) * 2;
            uint32_t Ah[2][4], Bh[2][4], Bl[2][4];
#pragma unroll
            for (int mi = 0; mi < 2; mi++) {
                uint32_t ad = smb + a_base + (uint32_t)mi * (16 * APAD * 2) + kb2;
                LDSM4(Ah[mi], ad + SM_A);
            }
#pragma unroll
            for (int nj = 0; nj < 2; nj++) {
                uint32_t bd = smb + b_base + (uint32_t)nj * (16 * APAD * 2) + kb2;
                LDSM4(Bh[nj], bd + SM_BH);
                LDSM4(Bl[nj], bd + SM_BL);
            }
#pragma unroll
            for (int mi = 0; mi < 2; mi++)
#pragma unroll
                for (int nj = 0; nj < 2; nj++) {
                    MMA_F16(acc[mi][2 * nj + 0], Ah[mi], Bh[nj][0], Bh[nj][1]);
                    MMA_F16(acc[mi][2 * nj + 0], Ah[mi], Bl[nj][0], Bl[nj][1]);
                    MMA_F16(acc[mi][2 * nj + 1], Ah[mi], Bh[nj][2], Bh[nj][3]);
                    MMA_F16(acc[mi][2 * nj + 1], Ah[mi], Bl[nj][2], Bl[nj][3]);
                }
        }
    }

    // ---- fused epilogues ----
    __syncthreads();
    float* st = (float*)sm;
    int g = lane >> 2, t = lane & 3;

    if (mode == 2) {
#pragma unroll
        for (int mi = 0; mi < 2; mi++)
#pragma unroll
            for (int ni = 0; ni < 4; ni++) {
                int r = wm + mi * 16 + g;
                int c = wn + ni * 8 + t * 2;
                st[c * 132 + r]           = acc[mi][ni][0];
                st[(c + 1) * 132 + r]     = acc[mi][ni][1];
                st[c * 132 + r + 8]       = acc[mi][ni][2];
                st[(c + 1) * 132 + r + 8] = acc[mi][ni][3];
            }
        __syncthreads();
        int seq = m0 >> 7;
        int b = seq >> 7, y = seq & 127;
#pragma unroll
        for (int j = 0; j < 32; j++) {
            int idx = j * 256 + tid;
            int c = idx >> 7, xx = idx & 127;
            outp[(((size_t)b * 128 + n0 + c) * 128 + y) * 128 + xx] = st[c * 132 + xx];
        }
        return;
    }

    // mode 1: stage [l][e] (pad 72)
#pragma unroll
    for (int mi = 0; mi < 2; mi++)
#pragma unroll
        for (int ni = 0; ni < 4; ni++) {
            int r = wm + mi * 16 + g;
            int c = wn + ni * 8 + t * 2;
            *(float2*)&st[r * 72 + c] = make_float2(acc[mi][ni][0], acc[mi][ni][1]);
            *(float2*)&st[(r + 8) * 72 + c] = make_float2(acc[mi][ni][2], acc[mi][ni][3]);
        }
    __syncthreads();

    if (n0 < 256) {
#pragma unroll
        for (int j = 0; j < 32; j++) {
            int idx = j * 256 + tid;
            int r = idx >> 6, c = idx & 63;
            g_z[(size_t)(m0 + r) * 256 + n0 + c] = st[r * 72 + c];
        }
    } else if (n0 < 640) {
        int e = tid & 63;
        int eg = n0 - 256 + e;
        float4 w4 = *(const float4*)(cw + eg * 4);
        float bia = __ldg(cb + eg);
        int lb = (tid >> 6) * 32;
        float x0 = (lb >= 3) ? st[(lb - 3) * 72 + e] : 0.0f;
        float x1 = (lb >= 2) ? st[(lb - 2) * 72 + e] : 0.0f;
        float x2 = (lb >= 1) ? st[(lb - 1) * 72 + e] : 0.0f;
#pragma unroll 8
        for (int l = lb; l < lb + 32; l++) {
            float x3 = st[l * 72 + e];
            float a = bia + w4.x * x0 + w4.y * x1 + w4.z * x2 + w4.w * x3;
            x0 = x1; x1 = x2; x2 = x3;
            g_xbcc[(size_t)(m0 + l) * 384 + eg] = a / (1.0f + expf(-a));
        }
    } else {
#pragma unroll
        for (int j = 0; j < 4; j++) {
            int idx = j * 256 + tid;
            int r = idx >> 3, hc = idx & 7;
            float v = st[r * 72 + hc] + __ldg(dtb + hc);
            g_dt[(size_t)(m0 + r) * 8 + hc] =
                fmaxf(v, 0.0f) + log1pf(expf(-fabsf(v)));
        }
    }
}

// ---------------------------------------------------------------------------
// K7: fused selective scan + gated RMSNorm.
// One block per sequence; thread = channel (hh*32+d == tid); full 64-state
// row in registers. Per-timestep block reduction normalizes immediately;
// writes fp16 y. No ys buffer.
// ---------------------------------------------------------------------------
#define SCANORM_SMEM ((8192 + 8192 + 1024 + 1024 + 16) * 4)
__global__ __launch_bounds__(256) void k_scanorm(const float* __restrict__ A_log,
                                                 const float* __restrict__ Dskip,
                                                 const float* __restrict__ ng) {
    extern __shared__ float smf[];
    float* sB  = smf;                 // [l*64+s]
    float* sC  = sB + 8192;
    float* sdt = sC + 8192;           // [l*8+h]
    float* sdA = sdt + 1024;
    float* pp  = sdA + 1024;          // [2][8]
    int bs = blockIdx.x;
    int t = threadIdx.x;
    int hh = t >> 5;
    int lane = t & 31, wid = t >> 5;

    const float* xb = g_xbcc + (size_t)bs * 128 * 384;
    for (int i = t; i < 8192; i += 256) {
        int l = i >> 6, s = i & 63;
        sB[i] = xb[l * 384 + 256 + s];
        sC[i] = xb[l * 384 + 320 + s];
    }
    for (int i = t; i < 1024; i += 256) {
        int l = i >> 3, h = i & 7;
        float v = g_dt[((size_t)bs * 128 + l) * 8 + h];
        sdt[i] = v;
        sdA[i] = expf(v * (-expf(__ldg(A_log + h))));
    }
    __syncthreads();

    float Dh = __ldg(Dskip + hh);
    float gn = __ldg(ng + t);
    float h[64];
#pragma unroll
    for (int s = 0; s < 64; s++) h[s] = 0.0f;
    __half* yh = (__half*)g_y_h;

    for (int l = 0; l < 128; l++) {
        float xv  = xb[l * 384 + t];                         // x channel = t
        float z   = g_z[((size_t)bs * 128 + l) * 256 + t];
        float dtv = sdt[l * 8 + hh];
        float dA  = sdA[l * 8 + hh];
        float cf  = dtv * xv;
        const float2* B2 = (const float2*)(sB + l * 64);
        const float2* C2 = (const float2*)(sC + l * 64);
        float y0 = 0.0f, y1 = 0.0f;
#pragma unroll
        for (int s = 0; s < 32; s++) {
            float2 b = B2[s], c = C2[s];
            h[2 * s]     = h[2 * s]     * dA + cf * b.x;
            h[2 * s + 1] = h[2 * s + 1] * dA + cf * b.y;
            y0 += h[2 * s] * c.x;
            y1 += h[2 * s + 1] * c.y;
        }
        float y = (y0 + y1) + Dh * xv;
        float gv = y * (z / (1.0f + expf(-z)));
        float g2 = gv * gv;
#pragma unroll
        for (int o = 16; o > 0; o >>= 1) g2 += __shfl_xor_sync(0xffffffffu, g2, o);
        float* ppb = pp + (l & 1) * 8;
        if (lane == 0) ppb[wid] = g2;
        __syncthreads();
        float sum = ppb[0] + ppb[1] + ppb[2] + ppb[3] +
                    ppb[4] + ppb[5] + ppb[6] + ppb[7];
        float sc = rsqrtf(sum * (1.0f / 256.0f) + 1e-5f);
        yh[((size_t)bs * 128 + l) * 256 + t] = __float2half(gv * sc * gn);
        // next iteration writes the other pp buffer; no second barrier needed
    }
}

// ---------------------------------------------------------------------------
extern "C" void kernel_launch(void* const* d_in, const int* in_sizes, int n_in,
                              void* d_out, int out_size) {
    const float* x        = (const float*)d_in[0];
    const float* dw_w     = (const float*)d_in[1];
    const float* gn_g     = (const float*)d_in[2];
    const float* gn_b     = (const float*)d_in[3];
    const float* pw_w     = (const float*)d_in[4];
    const float* pw_b     = (const float*)d_in[5];
    const float* in_projw = (const float*)d_in[6];
    const float* conv_w   = (const float*)d_in[7];
    const float* conv_b   = (const float*)d_in[8];
    const float* dt_bias  = (const float*)d_in[9];
    const float* A_log    = (const float*)d_in[10];
    const float* D_skip   = (const float*)d_in[11];
    const float* norm_g   = (const float*)d_in[12];
    const float* out_w    = (const float*)d_in[13];
    float* out = (float*)d_out;

    float* p_off;
    uint4 *p_sh, *p_yh, *p_iph, *p_ipl, *p_owh, *p_owl;
    cudaGetSymbolAddress((void**)&p_off, g_off);
    cudaGetSymbolAddress((void**)&p_sh, g_seq_h);
    cudaGetSymbolAddress((void**)&p_yh, g_y_h);
    cudaGetSymbolAddress((void**)&p_iph, g_ipw_hi);
    cudaGetSymbolAddress((void**)&p_ipl, g_ipw_lo);
    cudaGetSymbolAddress((void**)&p_owh, g_ow_hi);
    cudaGetSymbolAddress((void**)&p_owl, g_ow_lo);

    cudaFuncSetAttribute(k_gemm, cudaFuncAttributeMaxDynamicSharedMemorySize, SMEM_GEMM);
    cudaFuncSetAttribute(k_scanorm, cudaFuncAttributeMaxDynamicSharedMemorySize, SCANORM_SMEM);

    k_dwconv<<<OUT2D_ELEMS / 256, 256>>>(x, dw_w);
    k_gnstats1<<<dim3(64, 8), 256>>>();
    k_offset<<<OFF_ELEMS / 256, 256>>>(gn_g, gn_b, pw_w, pw_b);
    k_sample<<<dim3(BS, 2), 256>>>(x);
    k_wsplit<<<(IPW_ELEMS + 255) / 256, 256>>>(in_projw, p_iph, p_ipl, IPW_ELEMS);

    // in_proj: (M=131072, N=648, K=128) + fused conv1d/silu/dt epilogue
    k_gemm<<<dim3((D_INPROJ + 63) / 64, MM / 128), 256, SMEM_GEMM>>>(
        p_sh, p_iph, p_ipl, nullptr, conv_w, conv_b, dt_bias,
        D_INPROJ, 128, 1);

    k_wsplit<<<(OW_ELEMS + 255) / 256, 256>>>(out_w, p_owh, p_owl, OW_ELEMS);

    // fused scan + gated RMSNorm
    k_scanorm<<<BS, 256, SCANORM_SMEM>>>(A_log, D_skip, norm_g);

    // out proj: (M=131072, N=128, K=256) + fused NCHW epilogue
    k_gemm<<<dim3(2, MM / 128), 256, SMEM_GEMM>>>(
        p_yh, p_owh, p_owl, out, nullptr, nullptr, nullptr,
        128, 256, 2);

    if (out_size >= OUT2D_ELEMS + OFF_ELEMS)
        cudaMemcpyAsync(out + OUT2D_ELEMS, p_off, OFF_ELEMS * sizeof(float),
                        cudaMemcpyDeviceToDevice);
}